// round 3
// baseline (speedup 1.0000x reference)
#include <cuda_runtime.h>
#include <math.h>

#define NN 100000
#define NE 1600000
#define DD 128
#define CC 40
#define NL 3

// Static device scratch (allocation-free rule)
__device__ float g_h[(size_t)NN * DD];
__device__ float g_c2[(size_t)NN * DD];
__device__ float g_agg[(size_t)NN * DD];
__device__ float g_dinv[NN];

typedef unsigned long long u64;

__device__ __forceinline__ float siluf(float x) { return x / (1.0f + expf(-x)); }

__device__ __forceinline__ float warp_sum(float v) {
#pragma unroll
    for (int o = 16; o > 0; o >>= 1) v += __shfl_xor_sync(0xffffffffu, v, o);
    return v;
}

// Packed fp32x2 helpers (full-rate fp32 on sm_10x: FFMA-3reg is half rate)
__device__ __forceinline__ u64 dup2(float a) {
    u64 r; asm("mov.b64 %0, {%1, %1};" : "=l"(r) : "f"(a)); return r;
}
__device__ __forceinline__ void fma2(u64& d, u64 a, u64 b) {
    asm("fma.rn.f32x2 %0, %1, %2, %0;" : "+l"(d) : "l"(a), "l"(b));
}
__device__ __forceinline__ float2 unpk(u64 v) {
    float2 r; asm("mov.b64 {%0, %1}, %2;" : "=f"(r.x), "=f"(r.y) : "l"(v)); return r;
}

// ---------------- degree / dinv ----------------
__global__ void deg_init_kernel(float* __restrict__ deg) {
    int i = blockIdx.x * blockDim.x + threadIdx.x;
    if (i < NN) deg[i] = 1.0f;  // self loop
}
__global__ void deg_count_kernel(const int* __restrict__ col, float* __restrict__ deg) {
    int e = blockIdx.x * blockDim.x + threadIdx.x;
    if (e < NE) atomicAdd(&deg[col[e]], 1.0f);
}
__global__ void dinv_kernel(float* __restrict__ deg) {
    int i = blockIdx.x * blockDim.x + threadIdx.x;
    if (i < NN) deg[i] = rsqrtf(deg[i]);
}

// ---------------- fused LN + GEMM (D x D) ----------------
// MODE 0: out = silu(in @ W + bias)                      (start layer)
// MODE 1: out = LN(in; lng,lnb) @ W                      (pre-conv; bias added later)
// MODE 2: h1  = alpha_g * silu(agg + convB) + in         (agg already has self-loop)
//         out = alpha_f * silu(LN(h1) @ W + bias) + h1   (fused GCN-residual + FFN)
// Block: 256 threads, 64 rows. Thread (wid,lane) owns rows wid*8..+7, cols lane*4..+3.
template <int MODE>
__global__ void __launch_bounds__(256, 2) gemm128_kernel(
    const float* __restrict__ in,
    const float* __restrict__ W,      // [128][128] row-major (k, n)
    const float* __restrict__ bias,
    const float* __restrict__ lng,
    const float* __restrict__ lnb,
    const float* __restrict__ agg,
    const float* __restrict__ convB,
    const float* __restrict__ alpha_g,
    const float* __restrict__ alpha_f,
    float* __restrict__ out)
{
    __shared__ float Ash[64 * DD];
    const int tid  = threadIdx.x;
    const int wid  = tid >> 5;
    const int lane = tid & 31;
    const int row0 = blockIdx.x * 64;

    float4 h1v[8];  // MODE 2: raw h1 kept in registers (same lane-cols as epilogue)

    float4 g4 = make_float4(0.f, 0.f, 0.f, 0.f);
    float4 b4 = make_float4(0.f, 0.f, 0.f, 0.f);
    float4 cb4 = make_float4(0.f, 0.f, 0.f, 0.f);
    float ag = 0.f;
    if (MODE >= 1) {
        g4 = *(const float4*)(lng + lane * 4);
        b4 = *(const float4*)(lnb + lane * 4);
    }
    if (MODE == 2) {
        cb4 = *(const float4*)(convB + lane * 4);
        ag  = *alpha_g;
    }

    // ---- prologue: build (optionally LN'd) A tile in shared ----
#pragma unroll
    for (int i = 0; i < 8; i++) {
        const int lr = wid * 8 + i;
        const int r  = row0 + lr;
        float4 v = make_float4(0.f, 0.f, 0.f, 0.f);
        if (r < NN) v = *(const float4*)(in + (size_t)r * DD + lane * 4);
        if (MODE == 2) {
            float4 av = make_float4(0.f, 0.f, 0.f, 0.f);
            if (r < NN) av = *(const float4*)(agg + (size_t)r * DD + lane * 4);
            v.x = fmaf(ag, siluf(av.x + cb4.x), v.x);
            v.y = fmaf(ag, siluf(av.y + cb4.y), v.y);
            v.z = fmaf(ag, siluf(av.z + cb4.z), v.z);
            v.w = fmaf(ag, siluf(av.w + cb4.w), v.w);
            h1v[i] = v;
        }
        if (MODE >= 1) {
            float s1 = warp_sum(v.x + v.y + v.z + v.w);
            float s2 = warp_sum(v.x * v.x + v.y * v.y + v.z * v.z + v.w * v.w);
            float mu  = s1 * (1.0f / 128.0f);
            float var = fmaxf(s2 * (1.0f / 128.0f) - mu * mu, 0.0f);
            float rs  = rsqrtf(var + 1e-5f);
            v.x = (v.x - mu) * rs * g4.x + b4.x;
            v.y = (v.y - mu) * rs * g4.y + b4.y;
            v.z = (v.z - mu) * rs * g4.z + b4.z;
            v.w = (v.w - mu) * rs * g4.w + b4.w;
        }
        *(float4*)(Ash + lr * DD + lane * 4) = v;
    }
    __syncthreads();

    // ---- main loop: fp32x2 packed FMAs, W from L1 (64KB resident) ----
    u64 acc0[8], acc1[8];
#pragma unroll
    for (int i = 0; i < 8; i++) { acc0[i] = 0ull; acc1[i] = 0ull; }

    const float* Wp = W + lane * 4;
#pragma unroll 2
    for (int k0 = 0; k0 < DD; k0 += 4) {
        float4 a[8];
#pragma unroll
        for (int i = 0; i < 8; i++)
            a[i] = *(const float4*)(Ash + (wid * 8 + i) * DD + k0);
#pragma unroll
        for (int kk = 0; kk < 4; kk++) {
            const u64 b01 = *(const u64*)(Wp + (size_t)(k0 + kk) * DD);
            const u64 b23 = *(const u64*)(Wp + (size_t)(k0 + kk) * DD + 2);
#pragma unroll
            for (int i = 0; i < 8; i++) {
                float av = (kk == 0) ? a[i].x : (kk == 1) ? a[i].y : (kk == 2) ? a[i].z : a[i].w;
                u64 ad = dup2(av);
                fma2(acc0[i], ad, b01);
                fma2(acc1[i], ad, b23);
            }
        }
    }

    // ---- epilogue ----
    float4 bias4 = make_float4(0.f, 0.f, 0.f, 0.f);
    float af = 0.f;
    if (MODE == 0 || MODE == 2) bias4 = *(const float4*)(bias + lane * 4);
    if (MODE == 2) af = *alpha_f;

#pragma unroll
    for (int i = 0; i < 8; i++) {
        const int r = row0 + wid * 8 + i;
        if (r >= NN) continue;
        float2 o01 = unpk(acc0[i]);
        float2 o23 = unpk(acc1[i]);
        float4 o = make_float4(o01.x, o01.y, o23.x, o23.y);
        if (MODE == 0) {
            o.x = siluf(o.x + bias4.x);
            o.y = siluf(o.y + bias4.y);
            o.z = siluf(o.z + bias4.z);
            o.w = siluf(o.w + bias4.w);
        } else if (MODE == 2) {
            o.x = fmaf(af, siluf(o.x + bias4.x), h1v[i].x);
            o.y = fmaf(af, siluf(o.y + bias4.y), h1v[i].y);
            o.z = fmaf(af, siluf(o.z + bias4.z), h1v[i].z);
            o.w = fmaf(af, siluf(o.w + bias4.w), h1v[i].w);
        }
        *(float4*)(out + (size_t)r * DD + lane * 4) = o;
    }
}

// ---------------- agg init: self-loop term (also zeroes via overwrite) ----------------
__global__ void init_agg_kernel(const float* __restrict__ c2,
                                const float* __restrict__ dinv,
                                float* __restrict__ agg)
{
    const int idx = blockIdx.x * blockDim.x + threadIdx.x;  // over NN*32 float4
    if (idx >= NN * 32) return;
    const int r = idx >> 5;
    const float d = dinv[r];
    const float w = d * d;
    float4 v = ((const float4*)c2)[idx];
    v.x *= w; v.y *= w; v.z *= w; v.w *= w;
    ((float4*)agg)[idx] = v;
}

// ---------------- edge scatter: warp per edge, vector reduction ----------------
__global__ void __launch_bounds__(256) scatter_kernel(
    const int* __restrict__ rowi, const int* __restrict__ coli,
    const float* __restrict__ dinv, const float* __restrict__ c2,
    float* __restrict__ agg)
{
    const int e = blockIdx.x * 8 + (threadIdx.x >> 5);
    if (e >= NE) return;
    const int lane = threadIdx.x & 31;
    const int r = __ldg(rowi + e);
    const int c = __ldg(coli + e);
    const float w = __ldg(dinv + r) * __ldg(dinv + c);
    float4 v = *(const float4*)(c2 + (size_t)r * DD + lane * 4);
    float* dst = agg + (size_t)c * DD + lane * 4;
    asm volatile("red.global.add.v4.f32 [%0], {%1, %2, %3, %4};"
                 :: "l"(dst), "f"(v.x * w), "f"(v.y * w), "f"(v.z * w), "f"(v.w * w)
                 : "memory");
}

// ---------------- final: logits (128x40) + log_softmax ----------------
__global__ void __launch_bounds__(128) final_kernel(
    const float* __restrict__ h, const float* __restrict__ Wf,
    const float* __restrict__ fb, float* __restrict__ out)
{
    __shared__ float Wsh[DD * CC];
    __shared__ float bsh[CC];
    __shared__ float rowbuf[4][DD];
    const int tid = threadIdx.x;
    for (int i = tid; i < DD * CC; i += 128) Wsh[i] = Wf[i];
    if (tid < CC) bsh[tid] = fb[tid];
    __syncthreads();

    const int wid = tid >> 5, lane = tid & 31;
    const int rbase = blockIdx.x * 32 + wid * 8;
    const bool has1 = (lane < CC - 32);  // lanes 0..7 also own col 32+lane

    for (int ri = 0; ri < 8; ri++) {
        const int r = rbase + ri;
        if (r >= NN) return;
        float4 v = *(const float4*)(h + (size_t)r * DD + lane * 4);
        *(float4*)(&rowbuf[wid][lane * 4]) = v;
        __syncwarp();

        float acc0 = bsh[lane];
        float acc1 = has1 ? bsh[32 + lane] : 0.f;
#pragma unroll 4
        for (int k = 0; k < DD; k++) {
            float hv = rowbuf[wid][k];
            acc0 = fmaf(hv, Wsh[k * CC + lane], acc0);
            if (has1) acc1 = fmaf(hv, Wsh[k * CC + 32 + lane], acc1);
        }
        float m = has1 ? fmaxf(acc0, acc1) : acc0;
#pragma unroll
        for (int o = 16; o > 0; o >>= 1) m = fmaxf(m, __shfl_xor_sync(0xffffffffu, m, o));
        float s = expf(acc0 - m) + (has1 ? expf(acc1 - m) : 0.f);
#pragma unroll
        for (int o = 16; o > 0; o >>= 1) s += __shfl_xor_sync(0xffffffffu, s, o);
        const float ls = logf(s);
        out[(size_t)r * CC + lane] = acc0 - m - ls;
        if (has1) out[(size_t)r * CC + 32 + lane] = acc1 - m - ls;
        __syncwarp();
    }
}

// ---------------- launch ----------------
extern "C" void kernel_launch(void* const* d_in, const int* in_sizes, int n_in,
                              void* d_out, int out_size)
{
    const float* x       = (const float*)d_in[0];
    const int*   ei      = (const int*)  d_in[1];
    const float* start_W = (const float*)d_in[2];
    const float* start_b = (const float*)d_in[3];
    const float* ln1_g   = (const float*)d_in[4];
    const float* ln1_b   = (const float*)d_in[5];
    const float* convW   = (const float*)d_in[6];
    const float* convB   = (const float*)d_in[7];
    const float* alpha_g = (const float*)d_in[8];
    const float* ln2_g   = (const float*)d_in[9];
    const float* ln2_b   = (const float*)d_in[10];
    const float* ffwW    = (const float*)d_in[11];
    const float* ffwB    = (const float*)d_in[12];
    const float* alpha_f = (const float*)d_in[13];
    const float* final_W = (const float*)d_in[14];
    const float* final_b = (const float*)d_in[15];
    float* out = (float*)d_out;

    float *h, *c2, *agg, *dinv;
    cudaGetSymbolAddress((void**)&h,    g_h);
    cudaGetSymbolAddress((void**)&c2,   g_c2);
    cudaGetSymbolAddress((void**)&agg,  g_agg);
    cudaGetSymbolAddress((void**)&dinv, g_dinv);

    const int* rowi = ei;
    const int* coli = ei + NE;

    deg_init_kernel<<<(NN + 255) / 256, 256>>>(dinv);
    deg_count_kernel<<<(NE + 255) / 256, 256>>>(coli, dinv);
    dinv_kernel<<<(NN + 255) / 256, 256>>>(dinv);

    const int GB = (NN + 63) / 64;
    gemm128_kernel<0><<<GB, 256>>>(x, start_W, start_b, nullptr, nullptr,
                                   nullptr, nullptr, nullptr, nullptr, h);

    for (int i = 0; i < NL; i++) {
        gemm128_kernel<1><<<GB, 256>>>(h, convW + (size_t)i * DD * DD, nullptr,
                                       ln1_g + i * DD, ln1_b + i * DD,
                                       nullptr, nullptr, nullptr, nullptr, c2);
        init_agg_kernel<<<(NN * 32 + 255) / 256, 256>>>(c2, dinv, agg);
        scatter_kernel<<<(NE + 7) / 8, 256>>>(rowi, coli, dinv, c2, agg);
        gemm128_kernel<2><<<GB, 256>>>(h, ffwW + (size_t)i * DD * DD, ffwB + i * DD,
                                       ln2_g + i * DD, ln2_b + i * DD,
                                       agg, convB + i * DD,
                                       alpha_g + i, alpha_f + i, h);
    }

    final_kernel<<<(NN + 31) / 32, 128>>>(h, final_W, final_b, out);
}

// round 4
// speedup vs baseline: 1.3774x; 1.3774x over previous
#include <cuda_runtime.h>
#include <math.h>

#define NN 100000
#define NE 1600000
#define DD 128
#define CC 40
#define NL 3

// Static device scratch (allocation-free rule)
__device__ float g_h[(size_t)NN * DD];
__device__ float g_c2[(size_t)NN * DD];   // conv pre-agg output (row-scaled); reused as h1 scratch in MODE 2
__device__ float g_agg[(size_t)NN * DD];
__device__ float g_dinv[NN];
__device__ int   g_counts[NN];
__device__ int   g_off[NN + 1];
__device__ int   g_cur[NN];
__device__ int   g_eidx[NE];

typedef unsigned long long u64;

__device__ __forceinline__ float siluf(float x) { return x / (1.0f + expf(-x)); }

__device__ __forceinline__ float warp_sum(float v) {
#pragma unroll
    for (int o = 16; o > 0; o >>= 1) v += __shfl_xor_sync(0xffffffffu, v, o);
    return v;
}

// Packed fp32x2 helpers (full-rate fp32 on sm_10x; FFMA-3reg is half rate)
__device__ __forceinline__ u64 dup2(float a) {
    u64 r; asm("mov.b64 %0, {%1, %1};" : "=l"(r) : "f"(a)); return r;
}
__device__ __forceinline__ u64 pack2(float a, float b) {
    u64 r; asm("mov.b64 %0, {%1, %2};" : "=l"(r) : "f"(a), "f"(b)); return r;
}
__device__ __forceinline__ void fma2(u64& d, u64 a, u64 b) {
    asm("fma.rn.f32x2 %0, %1, %2, %0;" : "+l"(d) : "l"(a), "l"(b));
}
__device__ __forceinline__ float2 unpk(u64 v) {
    float2 r; asm("mov.b64 {%0, %1}, %2;" : "=f"(r.x), "=f"(r.y) : "l"(v)); return r;
}

// ---------------- CSR build ----------------
__global__ void zero_counts_kernel(int* __restrict__ counts) {
    int i = blockIdx.x * blockDim.x + threadIdx.x;
    if (i < NN) counts[i] = 0;
}
__global__ void count_kernel(const int* __restrict__ col, int* __restrict__ counts) {
    int e = blockIdx.x * blockDim.x + threadIdx.x;
    if (e < NE) atomicAdd(&counts[col[e]], 1);
}
__global__ void dinv_kernel(const int* __restrict__ counts, float* __restrict__ dinv) {
    int i = blockIdx.x * blockDim.x + threadIdx.x;
    if (i < NN) dinv[i] = rsqrtf((float)(counts[i] + 1));  // +1 self loop
}
// Single-block scan over NN counts -> off (exclusive in off[i], inclusive at off[i+1]); cur[i]=off[i]
__global__ void __launch_bounds__(1024) scan_kernel(const int* __restrict__ counts,
                                                    int* __restrict__ off,
                                                    int* __restrict__ cur) {
    __shared__ int wsum[32];
    __shared__ int s_carry;
    const int t = threadIdx.x, lane = t & 31, w = t >> 5;
    if (t == 0) { s_carry = 0; off[0] = 0; }
    __syncthreads();
    for (int base = 0; base < NN; base += 1024) {
        const int i = base + t;
        const int v = (i < NN) ? counts[i] : 0;
        int x = v;
#pragma unroll
        for (int o = 1; o < 32; o <<= 1) { int y = __shfl_up_sync(0xffffffffu, x, o); if (lane >= o) x += y; }
        if (lane == 31) wsum[w] = x;
        __syncthreads();
        if (w == 0) {
            int y = wsum[lane];
#pragma unroll
            for (int o = 1; o < 32; o <<= 1) { int z = __shfl_up_sync(0xffffffffu, y, o); if (lane >= o) y += z; }
            wsum[lane] = y;
        }
        __syncthreads();
        const int incl = x + (w > 0 ? wsum[w - 1] : 0) + s_carry;
        if (i < NN) { off[i + 1] = incl; cur[i] = incl - v; }
        __syncthreads();
        if (t == 1023) s_carry = incl;
        __syncthreads();
    }
}
__global__ void fill_kernel(const int* __restrict__ rowi, const int* __restrict__ coli,
                            int* __restrict__ cur, int* __restrict__ eidx) {
    int e = blockIdx.x * blockDim.x + threadIdx.x;
    if (e < NE) {
        int p = atomicAdd(&cur[coli[e]], 1);
        eidx[p] = rowi[e];
    }
}

// ---------------- fused LN + GEMM (128x128) ----------------
// MODE 0: out = silu(in @ W + bias)
// MODE 1: out[r] = (LN(in[r]) @ W) * dinv[r]            (row-scaled conv pre-agg)
// MODE 2: h1 = in + alpha_g * silu(agg + convB); out = alpha_f * silu(LN(h1) @ W + bias) + h1
//         (h1 round-trips via h1buf global scratch; visibility via __syncthreads within block)
// Block 256 thr = 8 warps, tile 64 rows x 128 cols.
// Compute mapping: warpRow = wid>>2 (0..1, 32 rows each), warpCol = wid&3 (0..3, 32 cols each)
//                  lane: rsub = lane>>3 (row sub, 8 rows each), csub = lane&7 (4 cols each)
template <int MODE>
__global__ void __launch_bounds__(256, 2) gemm128_kernel(
    const float* __restrict__ in,
    const float* __restrict__ W,
    const float* __restrict__ bias,
    const float* __restrict__ lng,
    const float* __restrict__ lnb,
    const float* __restrict__ agg,
    const float* __restrict__ convB,
    const float* __restrict__ alpha_g,
    const float* __restrict__ alpha_f,
    const float* __restrict__ dinv,
    float* __restrict__ h1buf,
    float* __restrict__ out)
{
    __shared__ float Ash[64 * DD];
    const int tid  = threadIdx.x;
    const int wid  = tid >> 5;
    const int lane = tid & 31;
    const int row0 = blockIdx.x * 64;

    // ---- prologue (mapping: warp = 8 rows, lane = 4 cols at lane*4) ----
    {
        float4 g4 = make_float4(0.f, 0.f, 0.f, 0.f);
        float4 b4 = make_float4(0.f, 0.f, 0.f, 0.f);
        float4 cb4 = make_float4(0.f, 0.f, 0.f, 0.f);
        float ag = 0.f;
        if (MODE >= 1) {
            g4 = *(const float4*)(lng + lane * 4);
            b4 = *(const float4*)(lnb + lane * 4);
        }
        if (MODE == 2) {
            cb4 = *(const float4*)(convB + lane * 4);
            ag  = *alpha_g;
        }
#pragma unroll
        for (int i = 0; i < 8; i++) {
            const int lr = wid * 8 + i;
            const int r  = row0 + lr;
            float4 v = make_float4(0.f, 0.f, 0.f, 0.f);
            if (r < NN) v = *(const float4*)(in + (size_t)r * DD + lane * 4);
            if (MODE == 2) {
                float4 av = make_float4(0.f, 0.f, 0.f, 0.f);
                if (r < NN) av = *(const float4*)(agg + (size_t)r * DD + lane * 4);
                v.x = fmaf(ag, siluf(av.x + cb4.x), v.x);
                v.y = fmaf(ag, siluf(av.y + cb4.y), v.y);
                v.z = fmaf(ag, siluf(av.z + cb4.z), v.z);
                v.w = fmaf(ag, siluf(av.w + cb4.w), v.w);
                if (r < NN) *(float4*)(h1buf + (size_t)r * DD + lane * 4) = v;  // raw h1
            }
            if (MODE >= 1) {
                float s1 = warp_sum(v.x + v.y + v.z + v.w);
                float s2 = warp_sum(v.x * v.x + v.y * v.y + v.z * v.z + v.w * v.w);
                float mu  = s1 * (1.0f / 128.0f);
                float var = fmaxf(s2 * (1.0f / 128.0f) - mu * mu, 0.0f);
                float rs  = rsqrtf(var + 1e-5f);
                v.x = (v.x - mu) * rs * g4.x + b4.x;
                v.y = (v.y - mu) * rs * g4.y + b4.y;
                v.z = (v.z - mu) * rs * g4.z + b4.z;
                v.w = (v.w - mu) * rs * g4.w + b4.w;
            }
            *(float4*)(Ash + lr * DD + lane * 4) = v;
        }
    }
    __syncthreads();

    // ---- main loop (2x4 warp grid; W loaded once per col-group pair) ----
    const int warpRow = wid >> 2;             // 0..1
    const int warpCol = wid & 3;              // 0..3
    const int rsub    = lane >> 3;            // 0..3
    const int csub    = lane & 7;             // 0..7
    const int rbase   = warpRow * 32 + rsub * 8;          // local row base (8 rows)
    const int c0      = warpCol * 32 + csub * 4;          // global col base (4 cols)

    u64 acc0[8], acc1[8];
#pragma unroll
    for (int i = 0; i < 8; i++) { acc0[i] = 0ull; acc1[i] = 0ull; }

#pragma unroll 2
    for (int k0 = 0; k0 < DD; k0 += 4) {
        float4 a[8];
#pragma unroll
        for (int i = 0; i < 8; i++)
            a[i] = *(const float4*)(Ash + (rbase + i) * DD + k0);
#pragma unroll
        for (int kk = 0; kk < 4; kk++) {
            const float4 b4 = *(const float4*)(W + (size_t)(k0 + kk) * DD + c0);
            const u64 b01 = pack2(b4.x, b4.y);
            const u64 b23 = pack2(b4.z, b4.w);
#pragma unroll
            for (int i = 0; i < 8; i++) {
                float av = (kk == 0) ? a[i].x : (kk == 1) ? a[i].y : (kk == 2) ? a[i].z : a[i].w;
                u64 ad = dup2(av);
                fma2(acc0[i], ad, b01);
                fma2(acc1[i], ad, b23);
            }
        }
    }

    // ---- epilogue ----
    float4 bias4 = make_float4(0.f, 0.f, 0.f, 0.f);
    float af = 0.f;
    if (MODE == 0 || MODE == 2) bias4 = *(const float4*)(bias + c0);
    if (MODE == 2) af = *alpha_f;

#pragma unroll
    for (int i = 0; i < 8; i++) {
        const int r = row0 + rbase + i;
        if (r >= NN) continue;
        float2 o01 = unpk(acc0[i]);
        float2 o23 = unpk(acc1[i]);
        float4 o = make_float4(o01.x, o01.y, o23.x, o23.y);
        if (MODE == 0) {
            o.x = siluf(o.x + bias4.x);
            o.y = siluf(o.y + bias4.y);
            o.z = siluf(o.z + bias4.z);
            o.w = siluf(o.w + bias4.w);
        } else if (MODE == 1) {
            const float dr = __ldg(dinv + r);
            o.x *= dr; o.y *= dr; o.z *= dr; o.w *= dr;
        } else {  // MODE 2
            const float4 h1 = *(const float4*)(h1buf + (size_t)r * DD + c0);
            o.x = fmaf(af, siluf(o.x + bias4.x), h1.x);
            o.y = fmaf(af, siluf(o.y + bias4.y), h1.y);
            o.z = fmaf(af, siluf(o.z + bias4.z), h1.z);
            o.w = fmaf(af, siluf(o.w + bias4.w), h1.w);
        }
        *(float4*)(out + (size_t)r * DD + c0) = o;
    }
}

// ---------------- CSR gather: warp per node, no atomics ----------------
// c2s[r] already contains c2[r]*dinv[r]; agg[n] = dinv[n] * (c2s[n] + sum_{r->n} c2s[r])
__global__ void __launch_bounds__(256) gather_kernel(
    const int* __restrict__ off, const int* __restrict__ eidx,
    const float* __restrict__ dinv, const float* __restrict__ c2s,
    float* __restrict__ agg)
{
    const int n = blockIdx.x * 8 + (threadIdx.x >> 5);
    if (n >= NN) return;
    const int lane = threadIdx.x & 31;
    const int s = __ldg(off + n);
    const int e = __ldg(off + n + 1);

    float4 acc = *(const float4*)(c2s + (size_t)n * DD + lane * 4);  // self-loop term
    for (int j0 = s; j0 < e; j0 += 32) {
        const int jn = min(32, e - j0);
        int eid = 0;
        if (lane < jn) eid = __ldg(eidx + j0 + lane);
        int t = 0;
        for (; t + 4 <= jn; t += 4) {
            const int r0 = __shfl_sync(0xffffffffu, eid, t);
            const int r1 = __shfl_sync(0xffffffffu, eid, t + 1);
            const int r2 = __shfl_sync(0xffffffffu, eid, t + 2);
            const int r3 = __shfl_sync(0xffffffffu, eid, t + 3);
            const float4 v0 = *(const float4*)(c2s + (size_t)r0 * DD + lane * 4);
            const float4 v1 = *(const float4*)(c2s + (size_t)r1 * DD + lane * 4);
            const float4 v2 = *(const float4*)(c2s + (size_t)r2 * DD + lane * 4);
            const float4 v3 = *(const float4*)(c2s + (size_t)r3 * DD + lane * 4);
            acc.x += v0.x + v1.x + v2.x + v3.x;
            acc.y += v0.y + v1.y + v2.y + v3.y;
            acc.z += v0.z + v1.z + v2.z + v3.z;
            acc.w += v0.w + v1.w + v2.w + v3.w;
        }
        for (; t < jn; t++) {
            const int r = __shfl_sync(0xffffffffu, eid, t);
            const float4 v = *(const float4*)(c2s + (size_t)r * DD + lane * 4);
            acc.x += v.x; acc.y += v.y; acc.z += v.z; acc.w += v.w;
        }
    }
    const float dn = __ldg(dinv + n);
    acc.x *= dn; acc.y *= dn; acc.z *= dn; acc.w *= dn;
    *(float4*)(agg + (size_t)n * DD + lane * 4) = acc;
}

// ---------------- final: logits (128x40) + log_softmax ----------------
__global__ void __launch_bounds__(128) final_kernel(
    const float* __restrict__ h, const float* __restrict__ Wf,
    const float* __restrict__ fb, float* __restrict__ out)
{
    __shared__ float Wsh[DD * CC];
    __shared__ float bsh[CC];
    __shared__ float rowbuf[4][DD];
    const int tid = threadIdx.x;
    for (int i = tid; i < DD * CC; i += 128) Wsh[i] = Wf[i];
    if (tid < CC) bsh[tid] = fb[tid];
    __syncthreads();

    const int wid = tid >> 5, lane = tid & 31;
    const int rbase = blockIdx.x * 32 + wid * 8;
    const bool has1 = (lane < CC - 32);

    for (int ri = 0; ri < 8; ri++) {
        const int r = rbase + ri;
        if (r >= NN) return;
        float4 v = *(const float4*)(h + (size_t)r * DD + lane * 4);
        *(float4*)(&rowbuf[wid][lane * 4]) = v;
        __syncwarp();

        float acc0 = bsh[lane];
        float acc1 = has1 ? bsh[32 + lane] : 0.f;
#pragma unroll 4
        for (int k = 0; k < DD; k++) {
            float hv = rowbuf[wid][k];
            acc0 = fmaf(hv, Wsh[k * CC + lane], acc0);
            if (has1) acc1 = fmaf(hv, Wsh[k * CC + 32 + lane], acc1);
        }
        float m = has1 ? fmaxf(acc0, acc1) : acc0;
#pragma unroll
        for (int o = 16; o > 0; o >>= 1) m = fmaxf(m, __shfl_xor_sync(0xffffffffu, m, o));
        float s = expf(acc0 - m) + (has1 ? expf(acc1 - m) : 0.f);
#pragma unroll
        for (int o = 16; o > 0; o >>= 1) s += __shfl_xor_sync(0xffffffffu, s, o);
        const float ls = logf(s);
        out[(size_t)r * CC + lane] = acc0 - m - ls;
        if (has1) out[(size_t)r * CC + 32 + lane] = acc1 - m - ls;
        __syncwarp();
    }
}

// ---------------- launch ----------------
extern "C" void kernel_launch(void* const* d_in, const int* in_sizes, int n_in,
                              void* d_out, int out_size)
{
    const float* x       = (const float*)d_in[0];
    const int*   ei      = (const int*)  d_in[1];
    const float* start_W = (const float*)d_in[2];
    const float* start_b = (const float*)d_in[3];
    const float* ln1_g   = (const float*)d_in[4];
    const float* ln1_b   = (const float*)d_in[5];
    const float* convW   = (const float*)d_in[6];
    const float* convB   = (const float*)d_in[7];
    const float* alpha_g = (const float*)d_in[8];
    const float* ln2_g   = (const float*)d_in[9];
    const float* ln2_b   = (const float*)d_in[10];
    const float* ffwW    = (const float*)d_in[11];
    const float* ffwB    = (const float*)d_in[12];
    const float* alpha_f = (const float*)d_in[13];
    const float* final_W = (const float*)d_in[14];
    const float* final_b = (const float*)d_in[15];
    float* out = (float*)d_out;

    float *h, *c2, *agg, *dinv;
    int *counts, *off, *cur, *eidx;
    cudaGetSymbolAddress((void**)&h,      g_h);
    cudaGetSymbolAddress((void**)&c2,     g_c2);
    cudaGetSymbolAddress((void**)&agg,    g_agg);
    cudaGetSymbolAddress((void**)&dinv,   g_dinv);
    cudaGetSymbolAddress((void**)&counts, g_counts);
    cudaGetSymbolAddress((void**)&off,    g_off);
    cudaGetSymbolAddress((void**)&cur,    g_cur);
    cudaGetSymbolAddress((void**)&eidx,   g_eidx);

    const int* rowi = ei;
    const int* coli = ei + NE;

    // CSR build (per call; deterministic work)
    zero_counts_kernel<<<(NN + 255) / 256, 256>>>(counts);
    count_kernel<<<(NE + 255) / 256, 256>>>(coli, counts);
    dinv_kernel<<<(NN + 255) / 256, 256>>>(counts, dinv);
    scan_kernel<<<1, 1024>>>(counts, off, cur);
    fill_kernel<<<(NE + 255) / 256, 256>>>(rowi, coli, cur, eidx);

    const int GB = (NN + 63) / 64;
    gemm128_kernel<0><<<GB, 256>>>(x, start_W, start_b, nullptr, nullptr,
                                   nullptr, nullptr, nullptr, nullptr, nullptr, nullptr, h);

    for (int i = 0; i < NL; i++) {
        // conv: c2 = LN1(h) @ convW, row-scaled by dinv
        gemm128_kernel<1><<<GB, 256>>>(h, convW + (size_t)i * DD * DD, nullptr,
                                       ln1_g + i * DD, ln1_b + i * DD,
                                       nullptr, nullptr, nullptr, nullptr, dinv, nullptr, c2);
        // aggregate (self loop folded in, no atomics)
        gather_kernel<<<(NN + 7) / 8, 256>>>(off, eidx, dinv, c2, agg);
        // fused GCN residual + FFN block (h1 scratch reuses c2 buffer — c2 dead after gather)
        gemm128_kernel<2><<<GB, 256>>>(h, ffwW + (size_t)i * DD * DD, ffwB + i * DD,
                                       ln2_g + i * DD, ln2_b + i * DD,
                                       agg, convB + i * DD,
                                       alpha_g + i, alpha_f + i, nullptr, c2, h);
    }

    final_kernel<<<(NN + 31) / 32, 128>>>(h, final_W, final_b, out);
}

// round 5
// speedup vs baseline: 1.4854x; 1.0784x over previous
#include <cuda_runtime.h>
#include <cuda_bf16.h>
#include <math.h>

#define NN 100000
#define NE 1600000
#define DD 128
#define CC 40
#define NL 3
#define NB_SCAN 98   // ceil(NN/1024)

// Static device scratch (allocation-free rule)
__device__ float          g_h[(size_t)NN * DD];
__device__ __nv_bfloat16  g_c2b[(size_t)NN * DD];   // row-scaled conv pre-agg (bf16; alpha-scaled path)
__device__ __nv_bfloat16  g_aggb[(size_t)NN * DD];  // aggregated messages (bf16; alpha-scaled path)
__device__ float g_dinv[NN];
__device__ int   g_counts[NN];
__device__ int   g_off[NN + 1];
__device__ int   g_cur[NN];
__device__ int   g_eidx[NE];
__device__ int   g_part[128];

typedef unsigned long long u64;
typedef unsigned int u32;

__device__ __forceinline__ float siluf(float x) { return x / (1.0f + expf(-x)); }

__device__ __forceinline__ float warp_sum(float v) {
#pragma unroll
    for (int o = 16; o > 0; o >>= 1) v += __shfl_xor_sync(0xffffffffu, v, o);
    return v;
}

// Packed fp32x2 helpers (full-rate fp32 on sm_10x; FFMA-3reg is half rate)
__device__ __forceinline__ u64 dup2(float a) {
    u64 r; asm("mov.b64 %0, {%1, %1};" : "=l"(r) : "f"(a)); return r;
}
__device__ __forceinline__ u64 pack2(float a, float b) {
    u64 r; asm("mov.b64 %0, {%1, %2};" : "=l"(r) : "f"(a), "f"(b)); return r;
}
__device__ __forceinline__ void fma2(u64& d, u64 a, u64 b) {
    asm("fma.rn.f32x2 %0, %1, %2, %0;" : "+l"(d) : "l"(a), "l"(b));
}
__device__ __forceinline__ float2 unpk(u64 v) {
    float2 r; asm("mov.b64 {%0, %1}, %2;" : "=f"(r.x), "=f"(r.y) : "l"(v)); return r;
}

// bf16x4 load/store (8 bytes)
__device__ __forceinline__ float4 ldb4(const __nv_bfloat16* p) {
    uint2 u = *(const uint2*)p;
    __nv_bfloat162 a = *reinterpret_cast<const __nv_bfloat162*>(&u.x);
    __nv_bfloat162 b = *reinterpret_cast<const __nv_bfloat162*>(&u.y);
    float2 fa = __bfloat1622float2(a);
    float2 fb = __bfloat1622float2(b);
    return make_float4(fa.x, fa.y, fb.x, fb.y);
}
__device__ __forceinline__ void stb4(__nv_bfloat16* p, float4 v) {
    __nv_bfloat162 a = __floats2bfloat162_rn(v.x, v.y);
    __nv_bfloat162 b = __floats2bfloat162_rn(v.z, v.w);
    uint2 u;
    u.x = *reinterpret_cast<u32*>(&a);
    u.y = *reinterpret_cast<u32*>(&b);
    *(uint2*)p = u;
}

// ---------------- CSR build ----------------
__global__ void zero_counts_kernel(int* __restrict__ counts) {
    int i = blockIdx.x * blockDim.x + threadIdx.x;
    if (i < NN) counts[i] = 0;
}
__global__ void count_kernel(const int* __restrict__ col, int* __restrict__ counts) {
    int e = blockIdx.x * blockDim.x + threadIdx.x;
    if (e < NE) atomicAdd(&counts[col[e]], 1);
}
__global__ void dinv_kernel(const int* __restrict__ counts, float* __restrict__ dinv) {
    int i = blockIdx.x * blockDim.x + threadIdx.x;
    if (i < NN) dinv[i] = rsqrtf((float)(counts[i] + 1));  // +1 self loop
}

// Phase A: per-block inclusive scan of counts chunk -> off[i+1] (local), part[b] = block total
__global__ void __launch_bounds__(1024) scan_block_kernel(const int* __restrict__ counts,
                                                          int* __restrict__ off,
                                                          int* __restrict__ part) {
    __shared__ int wsum[32];
    const int t = threadIdx.x, lane = t & 31, w = t >> 5;
    const int i = blockIdx.x * 1024 + t;
    const int v = (i < NN) ? counts[i] : 0;
    int x = v;
#pragma unroll
    for (int o = 1; o < 32; o <<= 1) { int y = __shfl_up_sync(0xffffffffu, x, o); if (lane >= o) x += y; }
    if (lane == 31) wsum[w] = x;
    __syncthreads();
    if (w == 0) {
        int y = wsum[lane];
#pragma unroll
        for (int o = 1; o < 32; o <<= 1) { int z = __shfl_up_sync(0xffffffffu, y, o); if (lane >= o) y += z; }
        wsum[lane] = y;
    }
    __syncthreads();
    const int incl = x + (w > 0 ? wsum[w - 1] : 0);
    if (i < NN) off[i + 1] = incl;
    if (t == 1023) part[blockIdx.x] = incl;
}
// Phase B: single warp exclusive-scans the 98 block partials in place; off[0]=0
__global__ void scan_part_kernel(int* __restrict__ part, int* __restrict__ off) {
    const int lane = threadIdx.x;
    int carry = 0;
    for (int base = 0; base < 128; base += 32) {
        const int idx = base + lane;
        const int v = (idx < NB_SCAN) ? part[idx] : 0;
        int x = v;
#pragma unroll
        for (int o = 1; o < 32; o <<= 1) { int y = __shfl_up_sync(0xffffffffu, x, o); if (lane >= o) x += y; }
        if (idx < NB_SCAN) part[idx] = carry + x - v;   // exclusive
        carry += __shfl_sync(0xffffffffu, x, 31);
    }
    if (lane == 0) off[0] = 0;
}
// Phase C: add carries; derive cur[i] = off[i] (exclusive start)
__global__ void add_carry_kernel(const int* __restrict__ counts,
                                 int* __restrict__ off,
                                 const int* __restrict__ part,
                                 int* __restrict__ cur) {
    const int i = blockIdx.x * blockDim.x + threadIdx.x;
    if (i >= NN) return;
    const int o = off[i + 1] + part[i >> 10];
    off[i + 1] = o;
    cur[i] = o - counts[i];
}
__global__ void fill_kernel(const int* __restrict__ rowi, const int* __restrict__ coli,
                            int* __restrict__ cur, int* __restrict__ eidx) {
    int e = blockIdx.x * blockDim.x + threadIdx.x;
    if (e < NE) {
        int p = atomicAdd(&cur[coli[e]], 1);
        eidx[p] = rowi[e];
    }
}

// ---------------- fused LN + GEMM (128x128) ----------------
// MODE 0: outf = silu(in @ W + bias)
// MODE 1: outb[r] = bf16( (LN(in[r]) @ W) * dinv[r] )        (row-scaled conv pre-agg)
// MODE 2: h1 = in + alpha_g * silu(agg + convB)  (recomputed in epilogue; never materialized)
//         outf = alpha_f * silu(LN(h1) @ W + bias) + h1
// Block 256 thr = 8 warps, tile 64 rows x 128 cols.
// Prologue mapping: warp = 8 rows, lane = cols lane*4.
// Compute mapping:  warpRow = wid>>2 (32 rows), warpCol = wid&3 (32 cols);
//                   lane: rsub = lane>>3 (8 rows), csub = lane&7 (4 cols).
template <int MODE>
__global__ void __launch_bounds__(256, 2) gemm128_kernel(
    const float* __restrict__ in,
    const float* __restrict__ W,
    const float* __restrict__ bias,
    const float* __restrict__ lng,
    const float* __restrict__ lnb,
    const __nv_bfloat16* __restrict__ aggb,
    const float* __restrict__ convB,
    const float* __restrict__ alpha_g,
    const float* __restrict__ alpha_f,
    const float* __restrict__ dinv,
    float* __restrict__ outf,
    __nv_bfloat16* __restrict__ outb)
{
    __shared__ float Ash[64 * DD];
    const int tid  = threadIdx.x;
    const int wid  = tid >> 5;
    const int lane = tid & 31;
    const int row0 = blockIdx.x * 64;

    float ag = 0.f;
    if (MODE == 2) ag = __ldg(alpha_g);

    // ---- prologue: build (optionally LN'd, MODE2: h1'd) A tile in shared ----
    {
        float4 g4 = make_float4(0.f, 0.f, 0.f, 0.f);
        float4 b4 = make_float4(0.f, 0.f, 0.f, 0.f);
        float4 cb4 = make_float4(0.f, 0.f, 0.f, 0.f);
        if (MODE >= 1) {
            g4 = *(const float4*)(lng + lane * 4);
            b4 = *(const float4*)(lnb + lane * 4);
        }
        if (MODE == 2) cb4 = *(const float4*)(convB + lane * 4);
#pragma unroll
        for (int i = 0; i < 8; i++) {
            const int lr = wid * 8 + i;
            const int r  = row0 + lr;
            float4 v = make_float4(0.f, 0.f, 0.f, 0.f);
            if (r < NN) v = *(const float4*)(in + (size_t)r * DD + lane * 4);
            if (MODE == 2) {
                float4 av = make_float4(0.f, 0.f, 0.f, 0.f);
                if (r < NN) av = ldb4(aggb + (size_t)r * DD + lane * 4);
                v.x = fmaf(ag, siluf(av.x + cb4.x), v.x);
                v.y = fmaf(ag, siluf(av.y + cb4.y), v.y);
                v.z = fmaf(ag, siluf(av.z + cb4.z), v.z);
                v.w = fmaf(ag, siluf(av.w + cb4.w), v.w);
            }
            if (MODE >= 1) {
                float s1 = warp_sum(v.x + v.y + v.z + v.w);
                float s2 = warp_sum(v.x * v.x + v.y * v.y + v.z * v.z + v.w * v.w);
                float mu  = s1 * (1.0f / 128.0f);
                float var = fmaxf(s2 * (1.0f / 128.0f) - mu * mu, 0.0f);
                float rs  = rsqrtf(var + 1e-5f);
                v.x = (v.x - mu) * rs * g4.x + b4.x;
                v.y = (v.y - mu) * rs * g4.y + b4.y;
                v.z = (v.z - mu) * rs * g4.z + b4.z;
                v.w = (v.w - mu) * rs * g4.w + b4.w;
            }
            *(float4*)(Ash + lr * DD + lane * 4) = v;
        }
    }
    __syncthreads();

    // ---- main loop (2x4 warp grid; packed fp32x2 FMAs, W via L1) ----
    const int warpRow = wid >> 2;
    const int warpCol = wid & 3;
    const int rsub    = lane >> 3;
    const int csub    = lane & 7;
    const int rbase   = warpRow * 32 + rsub * 8;
    const int c0      = warpCol * 32 + csub * 4;

    u64 acc0[8], acc1[8];
#pragma unroll
    for (int i = 0; i < 8; i++) { acc0[i] = 0ull; acc1[i] = 0ull; }

#pragma unroll 2
    for (int k0 = 0; k0 < DD; k0 += 4) {
        float4 a[8];
#pragma unroll
        for (int i = 0; i < 8; i++)
            a[i] = *(const float4*)(Ash + (rbase + i) * DD + k0);
#pragma unroll
        for (int kk = 0; kk < 4; kk++) {
            const float4 b4 = *(const float4*)(W + (size_t)(k0 + kk) * DD + c0);
            const u64 b01 = pack2(b4.x, b4.y);
            const u64 b23 = pack2(b4.z, b4.w);
#pragma unroll
            for (int i = 0; i < 8; i++) {
                float av = (kk == 0) ? a[i].x : (kk == 1) ? a[i].y : (kk == 2) ? a[i].z : a[i].w;
                u64 ad = dup2(av);
                fma2(acc0[i], ad, b01);
                fma2(acc1[i], ad, b23);
            }
        }
    }

    // ---- epilogue ----
    float4 bias4 = make_float4(0.f, 0.f, 0.f, 0.f);
    float4 cbe   = make_float4(0.f, 0.f, 0.f, 0.f);
    float af = 0.f;
    if (MODE == 0 || MODE == 2) bias4 = *(const float4*)(bias + c0);
    if (MODE == 2) {
        cbe = *(const float4*)(convB + c0);
        af  = __ldg(alpha_f);
    }

#pragma unroll
    for (int i = 0; i < 8; i++) {
        const int r = row0 + rbase + i;
        if (r >= NN) continue;
        float2 o01 = unpk(acc0[i]);
        float2 o23 = unpk(acc1[i]);
        float4 o = make_float4(o01.x, o01.y, o23.x, o23.y);
        if (MODE == 0) {
            o.x = siluf(o.x + bias4.x);
            o.y = siluf(o.y + bias4.y);
            o.z = siluf(o.z + bias4.z);
            o.w = siluf(o.w + bias4.w);
            *(float4*)(outf + (size_t)r * DD + c0) = o;
        } else if (MODE == 1) {
            const float dr = __ldg(dinv + r);
            o.x *= dr; o.y *= dr; o.z *= dr; o.w *= dr;
            stb4(outb + (size_t)r * DD + c0, o);
        } else {  // MODE 2: recompute h1 at (r, c0) from in/agg (bit-identical to prologue)
            const float4 in4 = *(const float4*)(in + (size_t)r * DD + c0);
            const float4 av  = ldb4(aggb + (size_t)r * DD + c0);
            float4 h1;
            h1.x = fmaf(ag, siluf(av.x + cbe.x), in4.x);
            h1.y = fmaf(ag, siluf(av.y + cbe.y), in4.y);
            h1.z = fmaf(ag, siluf(av.z + cbe.z), in4.z);
            h1.w = fmaf(ag, siluf(av.w + cbe.w), in4.w);
            o.x = fmaf(af, siluf(o.x + bias4.x), h1.x);
            o.y = fmaf(af, siluf(o.y + bias4.y), h1.y);
            o.z = fmaf(af, siluf(o.z + bias4.z), h1.z);
            o.w = fmaf(af, siluf(o.w + bias4.w), h1.w);
            *(float4*)(outf + (size_t)r * DD + c0) = o;
        }
    }
}

// ---------------- CSR gather: warp per node, bf16 payload, no atomics ----------------
// c2b[r] holds c2[r]*dinv[r] (bf16); aggb[n] = bf16( dinv[n] * (c2b[n] + sum_{r->n} c2b[r]) )
__global__ void __launch_bounds__(256) gather_kernel(
    const int* __restrict__ off, const int* __restrict__ eidx,
    const float* __restrict__ dinv, const __nv_bfloat16* __restrict__ c2b,
    __nv_bfloat16* __restrict__ aggb)
{
    const int n = blockIdx.x * 8 + (threadIdx.x >> 5);
    if (n >= NN) return;
    const int lane = threadIdx.x & 31;
    const int s = __ldg(off + n);
    const int e = __ldg(off + n + 1);

    float4 acc = ldb4(c2b + (size_t)n * DD + lane * 4);  // self-loop term
    for (int j0 = s; j0 < e; j0 += 32) {
        const int jn = min(32, e - j0);
        int eid = 0;
        if (lane < jn) eid = __ldg(eidx + j0 + lane);
        int t = 0;
        for (; t + 4 <= jn; t += 4) {
            const int r0 = __shfl_sync(0xffffffffu, eid, t);
            const int r1 = __shfl_sync(0xffffffffu, eid, t + 1);
            const int r2 = __shfl_sync(0xffffffffu, eid, t + 2);
            const int r3 = __shfl_sync(0xffffffffu, eid, t + 3);
            const float4 v0 = ldb4(c2b + (size_t)r0 * DD + lane * 4);
            const float4 v1 = ldb4(c2b + (size_t)r1 * DD + lane * 4);
            const float4 v2 = ldb4(c2b + (size_t)r2 * DD + lane * 4);
            const float4 v3 = ldb4(c2b + (size_t)r3 * DD + lane * 4);
            acc.x += v0.x + v1.x + v2.x + v3.x;
            acc.y += v0.y + v1.y + v2.y + v3.y;
            acc.z += v0.z + v1.z + v2.z + v3.z;
            acc.w += v0.w + v1.w + v2.w + v3.w;
        }
        for (; t < jn; t++) {
            const int r = __shfl_sync(0xffffffffu, eid, t);
            const float4 v = ldb4(c2b + (size_t)r * DD + lane * 4);
            acc.x += v.x; acc.y += v.y; acc.z += v.z; acc.w += v.w;
        }
    }
    const float dn = __ldg(dinv + n);
    acc.x *= dn; acc.y *= dn; acc.z *= dn; acc.w *= dn;
    stb4(aggb + (size_t)n * DD + lane * 4, acc);
}

// ---------------- final: logits (128x40) + log_softmax ----------------
__global__ void __launch_bounds__(128) final_kernel(
    const float* __restrict__ h, const float* __restrict__ Wf,
    const float* __restrict__ fb, float* __restrict__ out)
{
    __shared__ float Wsh[DD * CC];
    __shared__ float bsh[CC];
    __shared__ float rowbuf[4][DD];
    const int tid = threadIdx.x;
    for (int i = tid; i < DD * CC; i += 128) Wsh[i] = Wf[i];
    if (tid < CC) bsh[tid] = fb[tid];
    __syncthreads();

    const int wid = tid >> 5, lane = tid & 31;
    const int rbase = blockIdx.x * 32 + wid * 8;
    const bool has1 = (lane < CC - 32);

    for (int ri = 0; ri < 8; ri++) {
        const int r = rbase + ri;
        if (r >= NN) return;
        float4 v = *(const float4*)(h + (size_t)r * DD + lane * 4);
        *(float4*)(&rowbuf[wid][lane * 4]) = v;
        __syncwarp();

        float acc0 = bsh[lane];
        float acc1 = has1 ? bsh[32 + lane] : 0.f;
#pragma unroll 4
        for (int k = 0; k < DD; k++) {
            float hv = rowbuf[wid][k];
            acc0 = fmaf(hv, Wsh[k * CC + lane], acc0);
            if (has1) acc1 = fmaf(hv, Wsh[k * CC + 32 + lane], acc1);
        }
        float m = has1 ? fmaxf(acc0, acc1) : acc0;
#pragma unroll
        for (int o = 16; o > 0; o >>= 1) m = fmaxf(m, __shfl_xor_sync(0xffffffffu, m, o));
        float s = expf(acc0 - m) + (has1 ? expf(acc1 - m) : 0.f);
#pragma unroll
        for (int o = 16; o > 0; o >>= 1) s += __shfl_xor_sync(0xffffffffu, s, o);
        const float ls = logf(s);
        out[(size_t)r * CC + lane] = acc0 - m - ls;
        if (has1) out[(size_t)r * CC + 32 + lane] = acc1 - m - ls;
        __syncwarp();
    }
}

// ---------------- launch ----------------
extern "C" void kernel_launch(void* const* d_in, const int* in_sizes, int n_in,
                              void* d_out, int out_size)
{
    const float* x       = (const float*)d_in[0];
    const int*   ei      = (const int*)  d_in[1];
    const float* start_W = (const float*)d_in[2];
    const float* start_b = (const float*)d_in[3];
    const float* ln1_g   = (const float*)d_in[4];
    const float* ln1_b   = (const float*)d_in[5];
    const float* convW   = (const float*)d_in[6];
    const float* convB   = (const float*)d_in[7];
    const float* alpha_g = (const float*)d_in[8];
    const float* ln2_g   = (const float*)d_in[9];
    const float* ln2_b   = (const float*)d_in[10];
    const float* ffwW    = (const float*)d_in[11];
    const float* ffwB    = (const float*)d_in[12];
    const float* alpha_f = (const float*)d_in[13];
    const float* final_W = (const float*)d_in[14];
    const float* final_b = (const float*)d_in[15];
    float* out = (float*)d_out;

    float *h, *dinv;
    __nv_bfloat16 *c2b, *aggb;
    int *counts, *off, *cur, *eidx, *part;
    cudaGetSymbolAddress((void**)&h,      g_h);
    cudaGetSymbolAddress((void**)&c2b,    g_c2b);
    cudaGetSymbolAddress((void**)&aggb,   g_aggb);
    cudaGetSymbolAddress((void**)&dinv,   g_dinv);
    cudaGetSymbolAddress((void**)&counts, g_counts);
    cudaGetSymbolAddress((void**)&off,    g_off);
    cudaGetSymbolAddress((void**)&cur,    g_cur);
    cudaGetSymbolAddress((void**)&eidx,   g_eidx);
    cudaGetSymbolAddress((void**)&part,   g_part);

    const int* rowi = ei;
    const int* coli = ei + NE;

    // CSR build (fully parallel scan)
    zero_counts_kernel<<<(NN + 255) / 256, 256>>>(counts);
    count_kernel<<<(NE + 255) / 256, 256>>>(coli, counts);
    dinv_kernel<<<(NN + 255) / 256, 256>>>(counts, dinv);
    scan_block_kernel<<<NB_SCAN, 1024>>>(counts, off, part);
    scan_part_kernel<<<1, 32>>>(part, off);
    add_carry_kernel<<<(NN + 255) / 256, 256>>>(counts, off, part, cur);
    fill_kernel<<<(NE + 255) / 256, 256>>>(rowi, coli, cur, eidx);

    const int GB = (NN + 63) / 64;
    gemm128_kernel<0><<<GB, 256>>>(x, start_W, start_b, nullptr, nullptr,
                                   nullptr, nullptr, nullptr, nullptr, nullptr, h, nullptr);

    for (int i = 0; i < NL; i++) {
        // conv: c2b = bf16( LN1(h) @ convW * dinv[r] )
        gemm128_kernel<1><<<GB, 256>>>(h, convW + (size_t)i * DD * DD, nullptr,
                                       ln1_g + i * DD, ln1_b + i * DD,
                                       nullptr, nullptr, nullptr, nullptr, dinv, nullptr, c2b);
        // aggregate (self loop folded in, no atomics, bf16 payload)
        gather_kernel<<<(NN + 7) / 8, 256>>>(off, eidx, dinv, c2b, aggb);
        // fused GCN residual + FFN block (h1 recomputed in epilogue; no round-trip)
        gemm128_kernel<2><<<GB, 256>>>(h, ffwW + (size_t)i * DD * DD, ffwB + i * DD,
                                       ln2_g + i * DD, ln2_b + i * DD,
                                       aggb, convB + i * DD,
                                       alpha_g + i, alpha_f + i, nullptr, h, nullptr);
    }

    final_kernel<<<(NN + 31) / 32, 128>>>(h, final_W, final_b, out);
}

// round 6
// speedup vs baseline: 1.8572x; 1.2503x over previous
#include <cuda_runtime.h>
#include <cuda_bf16.h>
#include <math.h>

#define NN 100000
#define NE 1600000
#define DD 128
#define CC 40
#define NL 3
#define NB_SCAN 98   // ceil(NN/1024)

// Static device scratch (allocation-free rule)
__device__ float          g_h[(size_t)NN * DD];
__device__ __nv_bfloat16  g_c2b[(size_t)NN * DD];   // conv pre-agg (bf16)
__device__ __nv_bfloat16  g_aggb[(size_t)NN * DD];  // aggregated messages (bf16)
__device__ __nv_bfloat16  g_wb[6 * DD * DD];        // bf16 weights: [i]=convW_i, [3+i]=ffwW_i
__device__ float g_dinv[NN];
__device__ int   g_counts[NN];
__device__ int   g_off[NN + 1];
__device__ int   g_cur[NN];
__device__ int   g_eidx[NE];
__device__ int   g_part[128];

typedef unsigned long long u64;
typedef unsigned int u32;

__device__ __forceinline__ float siluf(float x) { return x / (1.0f + expf(-x)); }

__device__ __forceinline__ float warp_sum(float v) {
#pragma unroll
    for (int o = 16; o > 0; o >>= 1) v += __shfl_xor_sync(0xffffffffu, v, o);
    return v;
}

// Packed fp32x2 helpers (start GEMM stays fp32)
__device__ __forceinline__ u64 dup2(float a) {
    u64 r; asm("mov.b64 %0, {%1, %1};" : "=l"(r) : "f"(a)); return r;
}
__device__ __forceinline__ u64 pack2(float a, float b) {
    u64 r; asm("mov.b64 %0, {%1, %2};" : "=l"(r) : "f"(a), "f"(b)); return r;
}
__device__ __forceinline__ void fma2(u64& d, u64 a, u64 b) {
    asm("fma.rn.f32x2 %0, %1, %2, %0;" : "+l"(d) : "l"(a), "l"(b));
}
__device__ __forceinline__ float2 unpk(u64 v) {
    float2 r; asm("mov.b64 {%0, %1}, %2;" : "=f"(r.x), "=f"(r.y) : "l"(v)); return r;
}

// bf16x4 load/store (8 bytes)
__device__ __forceinline__ float4 ldb4(const __nv_bfloat16* p) {
    uint2 u = *(const uint2*)p;
    __nv_bfloat162 a = *reinterpret_cast<const __nv_bfloat162*>(&u.x);
    __nv_bfloat162 b = *reinterpret_cast<const __nv_bfloat162*>(&u.y);
    float2 fa = __bfloat1622float2(a);
    float2 fb = __bfloat1622float2(b);
    return make_float4(fa.x, fa.y, fb.x, fb.y);
}
__device__ __forceinline__ void stb4(__nv_bfloat16* p, float4 v) {
    __nv_bfloat162 a = __floats2bfloat162_rn(v.x, v.y);
    __nv_bfloat162 b = __floats2bfloat162_rn(v.z, v.w);
    uint2 u;
    u.x = *reinterpret_cast<u32*>(&a);
    u.y = *reinterpret_cast<u32*>(&b);
    *(uint2*)p = u;
}
__device__ __forceinline__ u32 pkbf2(float a, float b) {
    __nv_bfloat162 t = __floats2bfloat162_rn(a, b);
    return *reinterpret_cast<u32*>(&t);
}

// ---------------- weight conversion (once per call) ----------------
__global__ void convert_w_kernel(const float* __restrict__ convW,
                                 const float* __restrict__ ffwW,
                                 __nv_bfloat16* __restrict__ wb) {
    const int i = blockIdx.x * blockDim.x + threadIdx.x;
    const int per = NL * DD * DD;  // 49152
    if (i < per) wb[i] = __float2bfloat16(convW[i]);
    else if (i < 2 * per) wb[i] = __float2bfloat16(ffwW[i - per]);
}

// ---------------- CSR build ----------------
__global__ void zero_counts_kernel(int* __restrict__ counts) {
    int i = blockIdx.x * blockDim.x + threadIdx.x;
    if (i < NN) counts[i] = 0;
}
__global__ void count_kernel(const int* __restrict__ col, int* __restrict__ counts) {
    int e = blockIdx.x * blockDim.x + threadIdx.x;
    if (e < NE) atomicAdd(&counts[col[e]], 1);
}
__global__ void dinv_kernel(const int* __restrict__ counts, float* __restrict__ dinv) {
    int i = blockIdx.x * blockDim.x + threadIdx.x;
    if (i < NN) dinv[i] = rsqrtf((float)(counts[i] + 1));  // +1 self loop
}
__global__ void __launch_bounds__(1024) scan_block_kernel(const int* __restrict__ counts,
                                                          int* __restrict__ off,
                                                          int* __restrict__ part) {
    __shared__ int wsum[32];
    const int t = threadIdx.x, lane = t & 31, w = t >> 5;
    const int i = blockIdx.x * 1024 + t;
    const int v = (i < NN) ? counts[i] : 0;
    int x = v;
#pragma unroll
    for (int o = 1; o < 32; o <<= 1) { int y = __shfl_up_sync(0xffffffffu, x, o); if (lane >= o) x += y; }
    if (lane == 31) wsum[w] = x;
    __syncthreads();
    if (w == 0) {
        int y = wsum[lane];
#pragma unroll
        for (int o = 1; o < 32; o <<= 1) { int z = __shfl_up_sync(0xffffffffu, y, o); if (lane >= o) y += z; }
        wsum[lane] = y;
    }
    __syncthreads();
    const int incl = x + (w > 0 ? wsum[w - 1] : 0);
    if (i < NN) off[i + 1] = incl;
    if (t == 1023) part[blockIdx.x] = incl;
}
__global__ void scan_part_kernel(int* __restrict__ part, int* __restrict__ off) {
    const int lane = threadIdx.x;
    int carry = 0;
    for (int base = 0; base < 128; base += 32) {
        const int idx = base + lane;
        const int v = (idx < NB_SCAN) ? part[idx] : 0;
        int x = v;
#pragma unroll
        for (int o = 1; o < 32; o <<= 1) { int y = __shfl_up_sync(0xffffffffu, x, o); if (lane >= o) x += y; }
        if (idx < NB_SCAN) part[idx] = carry + x - v;
        carry += __shfl_sync(0xffffffffu, x, 31);
    }
    if (lane == 0) off[0] = 0;
}
__global__ void add_carry_kernel(const int* __restrict__ counts,
                                 int* __restrict__ off,
                                 const int* __restrict__ part,
                                 int* __restrict__ cur) {
    const int i = blockIdx.x * blockDim.x + threadIdx.x;
    if (i >= NN) return;
    const int o = off[i + 1] + part[i >> 10];
    off[i + 1] = o;
    cur[i] = o - counts[i];
}
__global__ void fill_kernel(const int* __restrict__ rowi, const int* __restrict__ coli,
                            int* __restrict__ cur, int* __restrict__ eidx) {
    int e = blockIdx.x * blockDim.x + threadIdx.x;
    if (e < NE) {
        int p = atomicAdd(&cur[coli[e]], 1);
        eidx[p] = rowi[e];
    }
}

// ---------------- start GEMM: fp32x2 (h written directly; keep exact) ----------------
__global__ void __launch_bounds__(256, 2) gemm0_kernel(
    const float* __restrict__ in, const float* __restrict__ W,
    const float* __restrict__ bias, float* __restrict__ outf)
{
    __shared__ float Ash[64 * DD];
    const int tid  = threadIdx.x;
    const int wid  = tid >> 5;
    const int lane = tid & 31;
    const int row0 = blockIdx.x * 64;

#pragma unroll
    for (int i = 0; i < 8; i++) {
        const int lr = wid * 8 + i;
        const int r  = row0 + lr;
        float4 v = make_float4(0.f, 0.f, 0.f, 0.f);
        if (r < NN) v = *(const float4*)(in + (size_t)r * DD + lane * 4);
        *(float4*)(Ash + lr * DD + lane * 4) = v;
    }
    __syncthreads();

    const int rbase = (wid >> 2) * 32 + (lane >> 3) * 8;
    const int c0    = (wid & 3) * 32 + (lane & 7) * 4;

    u64 acc0[8], acc1[8];
#pragma unroll
    for (int i = 0; i < 8; i++) { acc0[i] = 0ull; acc1[i] = 0ull; }

#pragma unroll 2
    for (int k0 = 0; k0 < DD; k0 += 4) {
        float4 a[8];
#pragma unroll
        for (int i = 0; i < 8; i++)
            a[i] = *(const float4*)(Ash + (rbase + i) * DD + k0);
#pragma unroll
        for (int kk = 0; kk < 4; kk++) {
            const float4 b4 = *(const float4*)(W + (size_t)(k0 + kk) * DD + c0);
            const u64 b01 = pack2(b4.x, b4.y);
            const u64 b23 = pack2(b4.z, b4.w);
#pragma unroll
            for (int i = 0; i < 8; i++) {
                float av = (kk == 0) ? a[i].x : (kk == 1) ? a[i].y : (kk == 2) ? a[i].z : a[i].w;
                u64 ad = dup2(av);
                fma2(acc0[i], ad, b01);
                fma2(acc1[i], ad, b23);
            }
        }
    }

    const float4 bias4 = *(const float4*)(bias + c0);
#pragma unroll
    for (int i = 0; i < 8; i++) {
        const int r = row0 + rbase + i;
        if (r >= NN) continue;
        float2 o01 = unpk(acc0[i]);
        float2 o23 = unpk(acc1[i]);
        float4 o;
        o.x = siluf(o01.x + bias4.x);
        o.y = siluf(o01.y + bias4.y);
        o.z = siluf(o23.x + bias4.z);
        o.w = siluf(o23.y + bias4.w);
        *(float4*)(outf + (size_t)r * DD + c0) = o;
    }
}

// ---------------- bf16 HMMA GEMM (layer GEMMs; outputs alpha-protected) ----------------
// MODE 1: outb = bf16( LN(in) @ Wb )                         (dinv applied in gather now)
// MODE 2: h1 = in + alpha_g*silu(agg+convB);  outf = alpha_f*silu(LN(h1)@Wb + bias) + h1
// Shared: Wsh[128][136] bf16 | Ash[64][136] bf16 | Csh[64][132] fp32  (dynamic, 86016 B)
#define WSH_OFF 0
#define ASH_OFF 34816
#define CSH_OFF 52224
#define GSMEM   86016
#define LDAB    136   // bf16 stride (272 B)
#define LDC     132   // fp32 stride

template <int MODE>
__global__ void __launch_bounds__(256, 2) gemm_bf16_kernel(
    const float* __restrict__ in,
    const __nv_bfloat16* __restrict__ Wb,
    const float* __restrict__ bias,
    const float* __restrict__ lng,
    const float* __restrict__ lnb,
    const __nv_bfloat16* __restrict__ aggb,
    const float* __restrict__ convB,
    const float* __restrict__ alpha_g,
    const float* __restrict__ alpha_f,
    float* __restrict__ outf,
    __nv_bfloat16* __restrict__ outb)
{
    extern __shared__ __align__(16) char smem[];
    __nv_bfloat16* Wsh = (__nv_bfloat16*)(smem + WSH_OFF);
    __nv_bfloat16* Ash = (__nv_bfloat16*)(smem + ASH_OFF);
    float*         Csh = (float*)(smem + CSH_OFF);

    const int tid  = threadIdx.x;
    const int wid  = tid >> 5;
    const int lane = tid & 31;
    const int row0 = blockIdx.x * 64;

    float ag = 0.f;
    if (MODE == 2) ag = __ldg(alpha_g);

    // ---- load W tile to shared (128 rows x 128 bf16, padded stride) ----
    {
        const int r = tid >> 1, half = tid & 1;
        const uint4* src = (const uint4*)(Wb + (size_t)r * DD + half * 64);
        uint4* dst = (uint4*)(Wsh + r * LDAB + half * 64);
#pragma unroll
        for (int j = 0; j < 8; j++) dst[j] = src[j];
    }

    // ---- prologue: LN (and MODE2 h1) in fp32, store bf16 A tile ----
    {
        const float4 g4 = *(const float4*)(lng + lane * 4);
        const float4 b4 = *(const float4*)(lnb + lane * 4);
        float4 cb4 = make_float4(0.f, 0.f, 0.f, 0.f);
        if (MODE == 2) cb4 = *(const float4*)(convB + lane * 4);
#pragma unroll
        for (int i = 0; i < 8; i++) {
            const int lr = wid * 8 + i;
            const int r  = row0 + lr;
            float4 v = make_float4(0.f, 0.f, 0.f, 0.f);
            if (r < NN) v = *(const float4*)(in + (size_t)r * DD + lane * 4);
            if (MODE == 2) {
                float4 av = make_float4(0.f, 0.f, 0.f, 0.f);
                if (r < NN) av = ldb4(aggb + (size_t)r * DD + lane * 4);
                v.x = fmaf(ag, siluf(av.x + cb4.x), v.x);
                v.y = fmaf(ag, siluf(av.y + cb4.y), v.y);
                v.z = fmaf(ag, siluf(av.z + cb4.z), v.z);
                v.w = fmaf(ag, siluf(av.w + cb4.w), v.w);
            }
            float s1 = warp_sum(v.x + v.y + v.z + v.w);
            float s2 = warp_sum(v.x * v.x + v.y * v.y + v.z * v.z + v.w * v.w);
            float mu  = s1 * (1.0f / 128.0f);
            float var = fmaxf(s2 * (1.0f / 128.0f) - mu * mu, 0.0f);
            float rs  = rsqrtf(var + 1e-5f);
            uint2 p;
            p.x = pkbf2((v.x - mu) * rs * g4.x + b4.x, (v.y - mu) * rs * g4.y + b4.y);
            p.y = pkbf2((v.z - mu) * rs * g4.z + b4.z, (v.w - mu) * rs * g4.w + b4.w);
            *(uint2*)(Ash + lr * LDAB + lane * 4) = p;
        }
    }
    __syncthreads();

    // ---- HMMA main: each warp computes 32x32; 2x4 warp grid ----
    const int m0 = (wid >> 2) * 32;
    const int n0 = (wid & 3) * 32;
    const u32 ash_base = (u32)__cvta_generic_to_shared(Ash);
    const u32 wsh_base = (u32)__cvta_generic_to_shared(Wsh);

    // ldmatrix lane address components
    const int a_i   = lane & 7;
    const int a_sel = lane >> 3;
    const int a_row = ((a_sel & 1) ? 8 : 0) + a_i;   // + mt*16 + m0
    const int a_kof = (a_sel & 2) ? 8 : 0;            // + k0
    const int b_row = lane & 15;                      // + k0 (lanes 16-31 replicate; ignored)

    float acc[2][4][4];
#pragma unroll
    for (int mt = 0; mt < 2; mt++)
#pragma unroll
        for (int nt = 0; nt < 4; nt++)
#pragma unroll
            for (int q = 0; q < 4; q++) acc[mt][nt][q] = 0.f;

#pragma unroll
    for (int k0 = 0; k0 < DD; k0 += 16) {
        u32 af[2][4];
#pragma unroll
        for (int mt = 0; mt < 2; mt++) {
            const u32 addr = ash_base + (u32)((m0 + mt * 16 + a_row) * (LDAB * 2) + (k0 + a_kof) * 2);
            asm volatile("ldmatrix.sync.aligned.m8n8.x4.shared.b16 {%0,%1,%2,%3}, [%4];"
                         : "=r"(af[mt][0]), "=r"(af[mt][1]), "=r"(af[mt][2]), "=r"(af[mt][3])
                         : "r"(addr));
        }
        u32 bf[4][2];
#pragma unroll
        for (int nt = 0; nt < 4; nt++) {
            const u32 addr = wsh_base + (u32)((k0 + b_row) * (LDAB * 2) + (n0 + nt * 8) * 2);
            asm volatile("ldmatrix.sync.aligned.m8n8.x2.trans.shared.b16 {%0,%1}, [%2];"
                         : "=r"(bf[nt][0]), "=r"(bf[nt][1]) : "r"(addr));
        }
#pragma unroll
        for (int mt = 0; mt < 2; mt++)
#pragma unroll
            for (int nt = 0; nt < 4; nt++) {
                asm volatile(
                    "mma.sync.aligned.m16n8k16.row.col.f32.bf16.bf16.f32 "
                    "{%0,%1,%2,%3}, {%4,%5,%6,%7}, {%8,%9}, {%0,%1,%2,%3};"
                    : "+f"(acc[mt][nt][0]), "+f"(acc[mt][nt][1]),
                      "+f"(acc[mt][nt][2]), "+f"(acc[mt][nt][3])
                    : "r"(af[mt][0]), "r"(af[mt][1]), "r"(af[mt][2]), "r"(af[mt][3]),
                      "r"(bf[nt][0]), "r"(bf[nt][1]));
            }
    }

    // ---- stage C in shared for coalesced epilogue ----
    {
        const int g = lane >> 2, t = lane & 3;
#pragma unroll
        for (int mt = 0; mt < 2; mt++)
#pragma unroll
            for (int nt = 0; nt < 4; nt++) {
                const int row = m0 + mt * 16 + g;
                const int col = n0 + nt * 8 + 2 * t;
                *(float2*)(Csh + row * LDC + col)       = make_float2(acc[mt][nt][0], acc[mt][nt][1]);
                *(float2*)(Csh + (row + 8) * LDC + col) = make_float2(acc[mt][nt][2], acc[mt][nt][3]);
            }
    }
    __syncthreads();

    // ---- epilogue (mapping: warp = 8 rows, lane = 4 cols) ----
    float4 bias4 = make_float4(0.f, 0.f, 0.f, 0.f);
    float4 cbe   = make_float4(0.f, 0.f, 0.f, 0.f);
    float af2 = 0.f;
    if (MODE == 2) {
        bias4 = *(const float4*)(bias + lane * 4);
        cbe   = *(const float4*)(convB + lane * 4);
        af2   = __ldg(alpha_f);
    }

#pragma unroll
    for (int i = 0; i < 8; i++) {
        const int lr = wid * 8 + i;
        const int r = row0 + lr;
        if (r >= NN) continue;
        float4 o = *(const float4*)(Csh + lr * LDC + lane * 4);
        if (MODE == 1) {
            stb4(outb + (size_t)r * DD + lane * 4, o);
        } else {
            const float4 in4 = *(const float4*)(in + (size_t)r * DD + lane * 4);
            const float4 av  = ldb4(aggb + (size_t)r * DD + lane * 4);
            float4 h1;
            h1.x = fmaf(ag, siluf(av.x + cbe.x), in4.x);
            h1.y = fmaf(ag, siluf(av.y + cbe.y), in4.y);
            h1.z = fmaf(ag, siluf(av.z + cbe.z), in4.z);
            h1.w = fmaf(ag, siluf(av.w + cbe.w), in4.w);
            o.x = fmaf(af2, siluf(o.x + bias4.x), h1.x);
            o.y = fmaf(af2, siluf(o.y + bias4.y), h1.y);
            o.z = fmaf(af2, siluf(o.z + bias4.z), h1.z);
            o.w = fmaf(af2, siluf(o.w + bias4.w), h1.w);
            *(float4*)(outf + (size_t)r * DD + lane * 4) = o;
        }
    }
}

// ---------------- CSR gather: warp per node; edge weight = dinv[r], node weight = dinv[n] ----------------
__global__ void __launch_bounds__(256) gather_kernel(
    const int* __restrict__ off, const int* __restrict__ eidx,
    const float* __restrict__ dinv, const __nv_bfloat16* __restrict__ c2b,
    __nv_bfloat16* __restrict__ aggb)
{
    const int n = blockIdx.x * 8 + (threadIdx.x >> 5);
    if (n >= NN) return;
    const int lane = threadIdx.x & 31;
    const int s = __ldg(off + n);
    const int e = __ldg(off + n + 1);
    const float dn = __ldg(dinv + n);

    float4 acc = ldb4(c2b + (size_t)n * DD + lane * 4);  // self-loop (weight dn folded below)
    acc.x *= dn; acc.y *= dn; acc.z *= dn; acc.w *= dn;
    for (int j0 = s; j0 < e; j0 += 32) {
        const int jn = min(32, e - j0);
        int eid = 0; float wv = 0.f;
        if (lane < jn) {
            eid = __ldg(eidx + j0 + lane);
            wv  = __ldg(dinv + eid);
        }
        int t = 0;
        for (; t + 4 <= jn; t += 4) {
            const int r0 = __shfl_sync(0xffffffffu, eid, t);
            const int r1 = __shfl_sync(0xffffffffu, eid, t + 1);
            const int r2 = __shfl_sync(0xffffffffu, eid, t + 2);
            const int r3 = __shfl_sync(0xffffffffu, eid, t + 3);
            const float w0 = __shfl_sync(0xffffffffu, wv, t);
            const float w1 = __shfl_sync(0xffffffffu, wv, t + 1);
            const float w2 = __shfl_sync(0xffffffffu, wv, t + 2);
            const float w3 = __shfl_sync(0xffffffffu, wv, t + 3);
            const float4 v0 = ldb4(c2b + (size_t)r0 * DD + lane * 4);
            const float4 v1 = ldb4(c2b + (size_t)r1 * DD + lane * 4);
            const float4 v2 = ldb4(c2b + (size_t)r2 * DD + lane * 4);
            const float4 v3 = ldb4(c2b + (size_t)r3 * DD + lane * 4);
            acc.x += w0 * v0.x + w1 * v1.x + w2 * v2.x + w3 * v3.x;
            acc.y += w0 * v0.y + w1 * v1.y + w2 * v2.y + w3 * v3.y;
            acc.z += w0 * v0.z + w1 * v1.z + w2 * v2.z + w3 * v3.z;
            acc.w += w0 * v0.w + w1 * v1.w + w2 * v2.w + w3 * v3.w;
        }
        for (; t < jn; t++) {
            const int r = __shfl_sync(0xffffffffu, eid, t);
            const float w = __shfl_sync(0xffffffffu, wv, t);
            const float4 v = ldb4(c2b + (size_t)r * DD + lane * 4);
            acc.x += w * v.x; acc.y += w * v.y; acc.z += w * v.z; acc.w += w * v.w;
        }
    }
    acc.x *= dn; acc.y *= dn; acc.z *= dn; acc.w *= dn;
    stb4(aggb + (size_t)n * DD + lane * 4, acc);
}

// ---------------- final: logits (128x40) + log_softmax ----------------
__global__ void __launch_bounds__(128) final_kernel(
    const float* __restrict__ h, const float* __restrict__ Wf,
    const float* __restrict__ fb, float* __restrict__ out)
{
    __shared__ float Wsh[DD * CC];
    __shared__ float bsh[CC];
    __shared__ float rowbuf[4][DD];
    const int tid = threadIdx.x;
    for (int i = tid; i < DD * CC; i += 128) Wsh[i] = Wf[i];
    if (tid < CC) bsh[tid] = fb[tid];
    __syncthreads();

    const int wid = tid >> 5, lane = tid & 31;
    const int rbase = blockIdx.x * 32 + wid * 8;
    const bool has1 = (lane < CC - 32);

    for (int ri = 0; ri < 8; ri++) {
        const int r = rbase + ri;
        if (r >= NN) return;
        float4 v = *(const float4*)(h + (size_t)r * DD + lane * 4);
        *(float4*)(&rowbuf[wid][lane * 4]) = v;
        __syncwarp();

        float acc0 = bsh[lane];
        float acc1 = has1 ? bsh[32 + lane] : 0.f;
#pragma unroll 4
        for (int k = 0; k < DD; k++) {
            float hv = rowbuf[wid][k];
            acc0 = fmaf(hv, Wsh[k * CC + lane], acc0);
            if (has1) acc1 = fmaf(hv, Wsh[k * CC + 32 + lane], acc1);
        }
        float m = has1 ? fmaxf(acc0, acc1) : acc0;
#pragma unroll
        for (int o = 16; o > 0; o >>= 1) m = fmaxf(m, __shfl_xor_sync(0xffffffffu, m, o));
        float s = expf(acc0 - m) + (has1 ? expf(acc1 - m) : 0.f);
#pragma unroll
        for (int o = 16; o > 0; o >>= 1) s += __shfl_xor_sync(0xffffffffu, s, o);
        const float ls = logf(s);
        out[(size_t)r * CC + lane] = acc0 - m - ls;
        if (has1) out[(size_t)r * CC + 32 + lane] = acc1 - m - ls;
        __syncwarp();
    }
}

// ---------------- launch ----------------
extern "C" void kernel_launch(void* const* d_in, const int* in_sizes, int n_in,
                              void* d_out, int out_size)
{
    const float* x       = (const float*)d_in[0];
    const int*   ei      = (const int*)  d_in[1];
    const float* start_W = (const float*)d_in[2];
    const float* start_b = (const float*)d_in[3];
    const float* ln1_g   = (const float*)d_in[4];
    const float* ln1_b   = (const float*)d_in[5];
    const float* convW   = (const float*)d_in[6];
    const float* convB   = (const float*)d_in[7];
    const float* alpha_g = (const float*)d_in[8];
    const float* ln2_g   = (const float*)d_in[9];
    const float* ln2_b   = (const float*)d_in[10];
    const float* ffwW    = (const float*)d_in[11];
    const float* ffwB    = (const float*)d_in[12];
    const float* alpha_f = (const float*)d_in[13];
    const float* final_W = (const float*)d_in[14];
    const float* final_b = (const float*)d_in[15];
    float* out = (float*)d_out;

    float *h, *dinv;
    __nv_bfloat16 *c2b, *aggb, *wb;
    int *counts, *off, *cur, *eidx, *part;
    cudaGetSymbolAddress((void**)&h,      g_h);
    cudaGetSymbolAddress((void**)&c2b,    g_c2b);
    cudaGetSymbolAddress((void**)&aggb,   g_aggb);
    cudaGetSymbolAddress((void**)&wb,     g_wb);
    cudaGetSymbolAddress((void**)&dinv,   g_dinv);
    cudaGetSymbolAddress((void**)&counts, g_counts);
    cudaGetSymbolAddress((void**)&off,    g_off);
    cudaGetSymbolAddress((void**)&cur,    g_cur);
    cudaGetSymbolAddress((void**)&eidx,   g_eidx);
    cudaGetSymbolAddress((void**)&part,   g_part);

    const int* rowi = ei;
    const int* coli = ei + NE;

    cudaFuncSetAttribute(gemm_bf16_kernel<1>, cudaFuncAttributeMaxDynamicSharedMemorySize, GSMEM);
    cudaFuncSetAttribute(gemm_bf16_kernel<2>, cudaFuncAttributeMaxDynamicSharedMemorySize, GSMEM);

    const int GB = (NN + 63) / 64;

    // Launch order chosen so ncu's captured launch (#4) is gemm_bf16<1>.
    convert_w_kernel<<<(2 * NL * DD * DD + 255) / 256, 256>>>(convW, ffwW, wb);       // 1
    gemm0_kernel<<<GB, 256>>>(x, start_W, start_b, h);                                 // 2
    zero_counts_kernel<<<(NN + 255) / 256, 256>>>(counts);                             // 3
    gemm_bf16_kernel<1><<<GB, 256, GSMEM>>>(h, wb, nullptr,                            // 4 (layer 0 conv)
                                            ln1_g, ln1_b, nullptr, nullptr,
                                            nullptr, nullptr, nullptr, c2b);
    count_kernel<<<(NE + 255) / 256, 256>>>(coli, counts);                             // 5
    dinv_kernel<<<(NN + 255) / 256, 256>>>(counts, dinv);                              // 6
    scan_block_kernel<<<NB_SCAN, 1024>>>(counts, off, part);                           // 7
    scan_part_kernel<<<1, 32>>>(part, off);                                            // 8
    add_carry_kernel<<<(NN + 255) / 256, 256>>>(counts, off, part, cur);               // 9
    fill_kernel<<<(NE + 255) / 256, 256>>>(rowi, coli, cur, eidx);                     // 10

    for (int i = 0; i < NL; i++) {
        if (i > 0) {
            gemm_bf16_kernel<1><<<GB, 256, GSMEM>>>(h, wb + (size_t)i * DD * DD, nullptr,
                                                    ln1_g + i * DD, ln1_b + i * DD,
                                                    nullptr, nullptr, nullptr, nullptr,
                                                    nullptr, c2b);
        }
        gather_kernel<<<(NN + 7) / 8, 256>>>(off, eidx, dinv, c2b, aggb);
        gemm_bf16_kernel<2><<<GB, 256, GSMEM>>>(h, wb + (size_t)(NL + i) * DD * DD, ffwB + i * DD,
                                                ln2_g + i * DD, ln2_b + i * DD,
                                                aggb, convB + i * DD,
                                                alpha_g + i, alpha_f + i, h, nullptr);
    }

    final_kernel<<<(NN + 31) / 32, 128>>>(h, final_W, final_b, out);
}

// round 7
// speedup vs baseline: 2.0211x; 1.0882x over previous
#include <cuda_runtime.h>
#include <cuda_bf16.h>
#include <math.h>

#define NN 100000
#define NE 1600000
#define DD 128
#define CC 40
#define NL 3
#define NB_SCAN 98   // ceil(NN/1024)

// Static device scratch (allocation-free rule)
__device__ float          g_h[(size_t)NN * DD];
__device__ __nv_bfloat16  g_c2b[(size_t)NN * DD];
__device__ __nv_bfloat16  g_aggb[(size_t)NN * DD];
__device__ __nv_bfloat16  g_wb[6 * DD * DD];     // layer weights bf16
__device__ __nv_bfloat16  g_w0hi[DD * DD];       // start_W split
__device__ __nv_bfloat16  g_w0lo[DD * DD];
__device__ float g_dinv[NN];
__device__ int   g_counts[NN];
__device__ int   g_off[NN + 1];
__device__ int   g_cur[NN];
__device__ int   g_eidx[NE];
__device__ int   g_part[128];

typedef unsigned long long u64;
typedef unsigned int u32;

__device__ __forceinline__ float siluf(float x) { return x / (1.0f + expf(-x)); }

__device__ __forceinline__ float warp_sum(float v) {
#pragma unroll
    for (int o = 16; o > 0; o >>= 1) v += __shfl_xor_sync(0xffffffffu, v, o);
    return v;
}

// bf16x4 load/store
__device__ __forceinline__ float4 ldb4(const __nv_bfloat16* p) {
    uint2 u = *(const uint2*)p;
    __nv_bfloat162 a = *reinterpret_cast<const __nv_bfloat162*>(&u.x);
    __nv_bfloat162 b = *reinterpret_cast<const __nv_bfloat162*>(&u.y);
    float2 fa = __bfloat1622float2(a);
    float2 fb = __bfloat1622float2(b);
    return make_float4(fa.x, fa.y, fb.x, fb.y);
}
__device__ __forceinline__ void stb4(__nv_bfloat16* p, float4 v) {
    __nv_bfloat162 a = __floats2bfloat162_rn(v.x, v.y);
    __nv_bfloat162 b = __floats2bfloat162_rn(v.z, v.w);
    uint2 u;
    u.x = *reinterpret_cast<u32*>(&a);
    u.y = *reinterpret_cast<u32*>(&b);
    *(uint2*)p = u;
}
__device__ __forceinline__ u32 pkbf2(float a, float b) {
    __nv_bfloat162 t = __floats2bfloat162_rn(a, b);
    return *reinterpret_cast<u32*>(&t);
}

// HMMA primitives
__device__ __forceinline__ void ldsm4(u32* f, u32 addr) {
    asm volatile("ldmatrix.sync.aligned.m8n8.x4.shared.b16 {%0,%1,%2,%3}, [%4];"
                 : "=r"(f[0]), "=r"(f[1]), "=r"(f[2]), "=r"(f[3]) : "r"(addr));
}
__device__ __forceinline__ void ldsm2t(u32* f, u32 addr) {
    asm volatile("ldmatrix.sync.aligned.m8n8.x2.trans.shared.b16 {%0,%1}, [%2];"
                 : "=r"(f[0]), "=r"(f[1]) : "r"(addr));
}
__device__ __forceinline__ void mma16816(float* c, const u32* a, const u32* b) {
    asm volatile("mma.sync.aligned.m16n8k16.row.col.f32.bf16.bf16.f32 "
                 "{%0,%1,%2,%3}, {%4,%5,%6,%7}, {%8,%9}, {%0,%1,%2,%3};"
                 : "+f"(c[0]), "+f"(c[1]), "+f"(c[2]), "+f"(c[3])
                 : "r"(a[0]), "r"(a[1]), "r"(a[2]), "r"(a[3]), "r"(b[0]), "r"(b[1]));
}

// ---------------- weight conversion (once per call) ----------------
__global__ void convert_w_kernel(const float* __restrict__ startW,
                                 const float* __restrict__ convW,
                                 const float* __restrict__ ffwW,
                                 __nv_bfloat16* __restrict__ w0hi,
                                 __nv_bfloat16* __restrict__ w0lo,
                                 __nv_bfloat16* __restrict__ wb) {
    const int i = blockIdx.x * blockDim.x + threadIdx.x;
    const int s = DD * DD;          // 16384
    const int per = NL * DD * DD;   // 49152
    if (i < s) {
        float v = startW[i];
        __nv_bfloat16 hi = __float2bfloat16(v);
        w0hi[i] = hi;
        w0lo[i] = __float2bfloat16(v - __bfloat162float(hi));
    } else if (i < s + per) {
        wb[i - s] = __float2bfloat16(convW[i - s]);
    } else if (i < s + 2 * per) {
        wb[i - s] = __float2bfloat16(ffwW[i - s - per]);
    }
}

// ---------------- CSR build ----------------
__global__ void zero_counts_kernel(int* __restrict__ counts) {
    int i = blockIdx.x * blockDim.x + threadIdx.x;
    if (i < NN) counts[i] = 0;
}
__global__ void count_kernel(const int* __restrict__ col, int* __restrict__ counts) {
    int e = blockIdx.x * blockDim.x + threadIdx.x;
    if (e < NE) atomicAdd(&counts[col[e]], 1);
}
__global__ void dinv_kernel(const int* __restrict__ counts, float* __restrict__ dinv) {
    int i = blockIdx.x * blockDim.x + threadIdx.x;
    if (i < NN) dinv[i] = rsqrtf((float)(counts[i] + 1));
}
__global__ void __launch_bounds__(1024) scan_block_kernel(const int* __restrict__ counts,
                                                          int* __restrict__ off,
                                                          int* __restrict__ part) {
    __shared__ int wsum[32];
    const int t = threadIdx.x, lane = t & 31, w = t >> 5;
    const int i = blockIdx.x * 1024 + t;
    const int v = (i < NN) ? counts[i] : 0;
    int x = v;
#pragma unroll
    for (int o = 1; o < 32; o <<= 1) { int y = __shfl_up_sync(0xffffffffu, x, o); if (lane >= o) x += y; }
    if (lane == 31) wsum[w] = x;
    __syncthreads();
    if (w == 0) {
        int y = wsum[lane];
#pragma unroll
        for (int o = 1; o < 32; o <<= 1) { int z = __shfl_up_sync(0xffffffffu, y, o); if (lane >= o) y += z; }
        wsum[lane] = y;
    }
    __syncthreads();
    const int incl = x + (w > 0 ? wsum[w - 1] : 0);
    if (i < NN) off[i + 1] = incl;
    if (t == 1023) part[blockIdx.x] = incl;
}
__global__ void scan_part_kernel(int* __restrict__ part, int* __restrict__ off) {
    const int lane = threadIdx.x;
    int carry = 0;
    for (int base = 0; base < 128; base += 32) {
        const int idx = base + lane;
        const int v = (idx < NB_SCAN) ? part[idx] : 0;
        int x = v;
#pragma unroll
        for (int o = 1; o < 32; o <<= 1) { int y = __shfl_up_sync(0xffffffffu, x, o); if (lane >= o) x += y; }
        if (idx < NB_SCAN) part[idx] = carry + x - v;
        carry += __shfl_sync(0xffffffffu, x, 31);
    }
    if (lane == 0) off[0] = 0;
}
__global__ void add_carry_kernel(const int* __restrict__ counts,
                                 int* __restrict__ off,
                                 const int* __restrict__ part,
                                 int* __restrict__ cur) {
    const int i = blockIdx.x * blockDim.x + threadIdx.x;
    if (i >= NN) return;
    const int o = off[i + 1] + part[i >> 10];
    off[i + 1] = o;
    cur[i] = o - counts[i];
}
__global__ void fill_kernel(const int* __restrict__ rowi, const int* __restrict__ coli,
                            int* __restrict__ cur, int* __restrict__ eidx) {
    int e = blockIdx.x * blockDim.x + threadIdx.x;
    if (e < NE) {
        int p = atomicAdd(&cur[coli[e]], 1);
        eidx[p] = rowi[e];
    }
}

// ---------------- unified HMMA GEMM (128 cols, 64-row tiles) ----------------
// MODE 0: outf = silu(x @ (Whi+Wlo) + bias)        split-bf16 (3 MMA groups)
// MODE 1: outb = bf16( LN(in) @ W )                direct fragment store
// MODE 2: h1 = in + ag*silu(agg+convB) (stashed in smem);
//         outf = af*silu(LN(h1) @ W + bias) + h1
//
// Shared layouts (dynamic):
//  MODE0: Whi[0,34816) Wlo[34816,69632) Ahi[69632,87040) Alo[87040,104448); C overlays Whi
//  MODE1: W[0,34816) A[34816,52224)
//  MODE2: W[0,34816) A[34816,52224) H1[52224,86016); C overlays W
#define LDAB 136
#define LDC  132
#define SM_M0 104448
#define SM_M1 52224
#define SM_M2 86016

template <int MODE>
__global__ void __launch_bounds__(256, 2) gemm_bf16_kernel(
    const float* __restrict__ in,
    const __nv_bfloat16* __restrict__ Whi,
    const __nv_bfloat16* __restrict__ Wlo,
    const float* __restrict__ bias,
    const float* __restrict__ lng,
    const float* __restrict__ lnb,
    const __nv_bfloat16* __restrict__ aggb,
    const float* __restrict__ convB,
    const float* __restrict__ alpha_g,
    const float* __restrict__ alpha_f,
    float* __restrict__ outf,
    __nv_bfloat16* __restrict__ outb)
{
    extern __shared__ __align__(16) char smem[];
    __nv_bfloat16* Wsh  = (__nv_bfloat16*)(smem);
    __nv_bfloat16* Wlos = (__nv_bfloat16*)(smem + 34816);
    __nv_bfloat16* Ash  = (__nv_bfloat16*)(smem + (MODE == 0 ? 69632 : 34816));
    __nv_bfloat16* Alos = (__nv_bfloat16*)(smem + 87040);
    float*         H1sh = (float*)(smem + 52224);
    float*         Csh  = (float*)(smem);  // overlay (MODE 0/2 only, after sync)

    const int tid  = threadIdx.x;
    const int wid  = tid >> 5;
    const int lane = tid & 31;
    const int row0 = blockIdx.x * 64;

    float ag = 0.f;
    if (MODE == 2) ag = __ldg(alpha_g);

    // ---- W tile(s) to shared ----
    {
        const int r = tid >> 1, half = tid & 1;
        const uint4* src = (const uint4*)(Whi + (size_t)r * DD + half * 64);
        uint4* dst = (uint4*)(Wsh + r * LDAB + half * 64);
#pragma unroll
        for (int j = 0; j < 8; j++) dst[j] = src[j];
        if (MODE == 0) {
            const uint4* s2 = (const uint4*)(Wlo + (size_t)r * DD + half * 64);
            uint4* d2 = (uint4*)(Wlos + r * LDAB + half * 64);
#pragma unroll
            for (int j = 0; j < 8; j++) d2[j] = s2[j];
        }
    }

    // ---- prologue: build A tile(s) ----
    {
        float4 g4 = make_float4(0.f, 0.f, 0.f, 0.f);
        float4 b4 = make_float4(0.f, 0.f, 0.f, 0.f);
        float4 cb4 = make_float4(0.f, 0.f, 0.f, 0.f);
        if (MODE >= 1) {
            g4 = *(const float4*)(lng + lane * 4);
            b4 = *(const float4*)(lnb + lane * 4);
        }
        if (MODE == 2) cb4 = *(const float4*)(convB + lane * 4);
#pragma unroll
        for (int i = 0; i < 8; i++) {
            const int lr = wid * 8 + i;
            const int r  = row0 + lr;
            float4 v = make_float4(0.f, 0.f, 0.f, 0.f);
            if (r < NN) v = *(const float4*)(in + (size_t)r * DD + lane * 4);
            if (MODE == 0) {
                // split bf16: hi + lo
                __nv_bfloat16 hx = __float2bfloat16(v.x), hy = __float2bfloat16(v.y);
                __nv_bfloat16 hz = __float2bfloat16(v.z), hw = __float2bfloat16(v.w);
                uint2 phi;
                phi.x = pkbf2(__bfloat162float(hx), __bfloat162float(hy));
                phi.y = pkbf2(__bfloat162float(hz), __bfloat162float(hw));
                *(uint2*)(Ash + lr * LDAB + lane * 4) = phi;
                uint2 plo;
                plo.x = pkbf2(v.x - __bfloat162float(hx), v.y - __bfloat162float(hy));
                plo.y = pkbf2(v.z - __bfloat162float(hz), v.w - __bfloat162float(hw));
                *(uint2*)(Alos + lr * LDAB + lane * 4) = plo;
                continue;
            }
            if (MODE == 2) {
                float4 av = make_float4(0.f, 0.f, 0.f, 0.f);
                if (r < NN) av = ldb4(aggb + (size_t)r * DD + lane * 4);
                v.x = fmaf(ag, siluf(av.x + cb4.x), v.x);
                v.y = fmaf(ag, siluf(av.y + cb4.y), v.y);
                v.z = fmaf(ag, siluf(av.z + cb4.z), v.z);
                v.w = fmaf(ag, siluf(av.w + cb4.w), v.w);
                *(float4*)(H1sh + lr * LDC + lane * 4) = v;   // stash raw h1
            }
            float s1 = warp_sum(v.x + v.y + v.z + v.w);
            float s2 = warp_sum(v.x * v.x + v.y * v.y + v.z * v.z + v.w * v.w);
            float mu  = s1 * (1.0f / 128.0f);
            float var = fmaxf(s2 * (1.0f / 128.0f) - mu * mu, 0.0f);
            float rs  = rsqrtf(var + 1e-5f);
            uint2 p;
            p.x = pkbf2((v.x - mu) * rs * g4.x + b4.x, (v.y - mu) * rs * g4.y + b4.y);
            p.y = pkbf2((v.z - mu) * rs * g4.z + b4.z, (v.w - mu) * rs * g4.w + b4.w);
            *(uint2*)(Ash + lr * LDAB + lane * 4) = p;
        }
    }
    __syncthreads();

    // ---- HMMA mainloop: warp grid 2x4, warp tile 32x32 ----
    const int m0 = (wid >> 2) * 32;
    const int n0 = (wid & 3) * 32;
    const u32 a_base  = (u32)__cvta_generic_to_shared(Ash);
    const u32 al_base = (u32)__cvta_generic_to_shared(Alos);
    const u32 w_base  = (u32)__cvta_generic_to_shared(Wsh);
    const u32 wl_base = (u32)__cvta_generic_to_shared(Wlos);

    const int a_i   = lane & 7;
    const int a_sel = lane >> 3;
    const int a_row = ((a_sel & 1) ? 8 : 0) + a_i;
    const int a_kof = (a_sel & 2) ? 8 : 0;
    const int b_row = lane & 15;

    float acc[2][4][4];
#pragma unroll
    for (int mt = 0; mt < 2; mt++)
#pragma unroll
        for (int nt = 0; nt < 4; nt++)
#pragma unroll
            for (int q = 0; q < 4; q++) acc[mt][nt][q] = 0.f;

    if (MODE == 0) {
        // split: 3 MMA groups per k-step, single-buffered (24 mmas hide ldsm latency)
#pragma unroll
        for (int k0 = 0; k0 < DD; k0 += 16) {
            u32 ah[2][4], al[2][4], bh[4][2], bl[4][2];
#pragma unroll
            for (int mt = 0; mt < 2; mt++) {
                const u32 off = (u32)((m0 + mt * 16 + a_row) * (LDAB * 2) + (k0 + a_kof) * 2);
                ldsm4(ah[mt], a_base + off);
                ldsm4(al[mt], al_base + off);
            }
#pragma unroll
            for (int nt = 0; nt < 4; nt++) {
                const u32 off = (u32)((k0 + b_row) * (LDAB * 2) + (n0 + nt * 8) * 2);
                ldsm2t(bh[nt], w_base + off);
                ldsm2t(bl[nt], wl_base + off);
            }
#pragma unroll
            for (int mt = 0; mt < 2; mt++)
#pragma unroll
                for (int nt = 0; nt < 4; nt++) {
                    mma16816(acc[mt][nt], ah[mt], bh[nt]);
                    mma16816(acc[mt][nt], ah[mt], bl[nt]);
                    mma16816(acc[mt][nt], al[mt], bh[nt]);
                }
        }
    } else {
        // double-buffered software pipeline
        u32 af[2][2][4], bf[2][4][2];
#pragma unroll
        for (int mt = 0; mt < 2; mt++)
            ldsm4(af[0][mt], a_base + (u32)((m0 + mt * 16 + a_row) * (LDAB * 2) + a_kof * 2));
#pragma unroll
        for (int nt = 0; nt < 4; nt++)
            ldsm2t(bf[0][nt], w_base + (u32)(b_row * (LDAB * 2) + (n0 + nt * 8) * 2));
#pragma unroll
        for (int ks = 0; ks < 8; ks++) {
            const int cur = ks & 1;
            if (ks < 7) {
                const int k1 = (ks + 1) * 16;
#pragma unroll
                for (int mt = 0; mt < 2; mt++)
                    ldsm4(af[cur ^ 1][mt], a_base + (u32)((m0 + mt * 16 + a_row) * (LDAB * 2) + (k1 + a_kof) * 2));
#pragma unroll
                for (int nt = 0; nt < 4; nt++)
                    ldsm2t(bf[cur ^ 1][nt], w_base + (u32)((k1 + b_row) * (LDAB * 2) + (n0 + nt * 8) * 2));
            }
#pragma unroll
            for (int mt = 0; mt < 2; mt++)
#pragma unroll
                for (int nt = 0; nt < 4; nt++)
                    mma16816(acc[mt][nt], af[cur][mt], bf[cur][nt]);
        }
    }

    // ---- epilogue ----
    if (MODE == 1) {
        // direct bf16 fragment store (no staging, no extra barrier)
        const int g = lane >> 2, t = lane & 3;
#pragma unroll
        for (int mt = 0; mt < 2; mt++)
#pragma unroll
            for (int nt = 0; nt < 4; nt++) {
                const int col = n0 + nt * 8 + 2 * t;
                const int r0 = row0 + m0 + mt * 16 + g;
                const int r1 = r0 + 8;
                if (r0 < NN) *(u32*)(outb + (size_t)r0 * DD + col) = pkbf2(acc[mt][nt][0], acc[mt][nt][1]);
                if (r1 < NN) *(u32*)(outb + (size_t)r1 * DD + col) = pkbf2(acc[mt][nt][2], acc[mt][nt][3]);
            }
        return;
    }

    // MODE 0 / 2: stage C in shared (overlay W region) for coalesced fp32 epilogue
    __syncthreads();   // all warps done reading Wsh
    {
        const int g = lane >> 2, t = lane & 3;
#pragma unroll
        for (int mt = 0; mt < 2; mt++)
#pragma unroll
            for (int nt = 0; nt < 4; nt++) {
                const int row = m0 + mt * 16 + g;
                const int col = n0 + nt * 8 + 2 * t;
                *(float2*)(Csh + row * LDC + col)       = make_float2(acc[mt][nt][0], acc[mt][nt][1]);
                *(float2*)(Csh + (row + 8) * LDC + col) = make_float2(acc[mt][nt][2], acc[mt][nt][3]);
            }
    }
    __syncthreads();

    const float4 bias4 = *(const float4*)(bias + lane * 4);
    float af2 = 0.f;
    if (MODE == 2) af2 = __ldg(alpha_f);

#pragma unroll
    for (int i = 0; i < 8; i++) {
        const int lr = wid * 8 + i;
        const int r = row0 + lr;
        if (r >= NN) continue;
        float4 o = *(const float4*)(Csh + lr * LDC + lane * 4);
        if (MODE == 0) {
            o.x = siluf(o.x + bias4.x);
            o.y = siluf(o.y + bias4.y);
            o.z = siluf(o.z + bias4.z);
            o.w = siluf(o.w + bias4.w);
        } else {
            const float4 h1 = *(const float4*)(H1sh + lr * LDC + lane * 4);
            o.x = fmaf(af2, siluf(o.x + bias4.x), h1.x);
            o.y = fmaf(af2, siluf(o.y + bias4.y), h1.y);
            o.z = fmaf(af2, siluf(o.z + bias4.z), h1.z);
            o.w = fmaf(af2, siluf(o.w + bias4.w), h1.w);
        }
        *(float4*)(outf + (size_t)r * DD + lane * 4) = o;
    }
}

// ---------------- CSR gather: warp per node ----------------
__global__ void __launch_bounds__(256) gather_kernel(
    const int* __restrict__ off, const int* __restrict__ eidx,
    const float* __restrict__ dinv, const __nv_bfloat16* __restrict__ c2b,
    __nv_bfloat16* __restrict__ aggb)
{
    const int n = blockIdx.x * 8 + (threadIdx.x >> 5);
    if (n >= NN) return;
    const int lane = threadIdx.x & 31;
    const int s = __ldg(off + n);
    const int e = __ldg(off + n + 1);
    const float dn = __ldg(dinv + n);

    float4 acc = ldb4(c2b + (size_t)n * DD + lane * 4);
    acc.x *= dn; acc.y *= dn; acc.z *= dn; acc.w *= dn;
    for (int j0 = s; j0 < e; j0 += 32) {
        const int jn = min(32, e - j0);
        int eid = 0; float wv = 0.f;
        if (lane < jn) {
            eid = __ldg(eidx + j0 + lane);
            wv  = __ldg(dinv + eid);
        }
        int t = 0;
        for (; t + 4 <= jn; t += 4) {
            const int r0 = __shfl_sync(0xffffffffu, eid, t);
            const int r1 = __shfl_sync(0xffffffffu, eid, t + 1);
            const int r2 = __shfl_sync(0xffffffffu, eid, t + 2);
            const int r3 = __shfl_sync(0xffffffffu, eid, t + 3);
            const float w0 = __shfl_sync(0xffffffffu, wv, t);
            const float w1 = __shfl_sync(0xffffffffu, wv, t + 1);
            const float w2 = __shfl_sync(0xffffffffu, wv, t + 2);
            const float w3 = __shfl_sync(0xffffffffu, wv, t + 3);
            const float4 v0 = ldb4(c2b + (size_t)r0 * DD + lane * 4);
            const float4 v1 = ldb4(c2b + (size_t)r1 * DD + lane * 4);
            const float4 v2 = ldb4(c2b + (size_t)r2 * DD + lane * 4);
            const float4 v3 = ldb4(c2b + (size_t)r3 * DD + lane * 4);
            acc.x += w0 * v0.x + w1 * v1.x + w2 * v2.x + w3 * v3.x;
            acc.y += w0 * v0.y + w1 * v1.y + w2 * v2.y + w3 * v3.y;
            acc.z += w0 * v0.z + w1 * v1.z + w2 * v2.z + w3 * v3.z;
            acc.w += w0 * v0.w + w1 * v1.w + w2 * v2.w + w3 * v3.w;
        }
        for (; t < jn; t++) {
            const int r = __shfl_sync(0xffffffffu, eid, t);
            const float w = __shfl_sync(0xffffffffu, wv, t);
            const float4 v = ldb4(c2b + (size_t)r * DD + lane * 4);
            acc.x += w * v.x; acc.y += w * v.y; acc.z += w * v.z; acc.w += w * v.w;
        }
    }
    acc.x *= dn; acc.y *= dn; acc.z *= dn; acc.w *= dn;
    stb4(aggb + (size_t)n * DD + lane * 4, acc);
}

// ---------------- final: logits (128x40) + log_softmax ----------------
__global__ void __launch_bounds__(128) final_kernel(
    const float* __restrict__ h, const float* __restrict__ Wf,
    const float* __restrict__ fb, float* __restrict__ out)
{
    __shared__ float Wsh[DD * CC];
    __shared__ float bsh[CC];
    __shared__ float rowbuf[4][DD];
    const int tid = threadIdx.x;
    for (int i = tid; i < DD * CC; i += 128) Wsh[i] = Wf[i];
    if (tid < CC) bsh[tid] = fb[tid];
    __syncthreads();

    const int wid = tid >> 5, lane = tid & 31;
    const int rbase = blockIdx.x * 32 + wid * 8;
    const bool has1 = (lane < CC - 32);

    for (int ri = 0; ri < 8; ri++) {
        const int r = rbase + ri;
        if (r >= NN) return;
        float4 v = *(const float4*)(h + (size_t)r * DD + lane * 4);
        *(float4*)(&rowbuf[wid][lane * 4]) = v;
        __syncwarp();

        float acc0 = bsh[lane];
        float acc1 = has1 ? bsh[32 + lane] : 0.f;
#pragma unroll 4
        for (int k = 0; k < DD; k++) {
            float hv = rowbuf[wid][k];
            acc0 = fmaf(hv, Wsh[k * CC + lane], acc0);
            if (has1) acc1 = fmaf(hv, Wsh[k * CC + 32 + lane], acc1);
        }
        float m = has1 ? fmaxf(acc0, acc1) : acc0;
#pragma unroll
        for (int o = 16; o > 0; o >>= 1) m = fmaxf(m, __shfl_xor_sync(0xffffffffu, m, o));
        float s = expf(acc0 - m) + (has1 ? expf(acc1 - m) : 0.f);
#pragma unroll
        for (int o = 16; o > 0; o >>= 1) s += __shfl_xor_sync(0xffffffffu, s, o);
        const float ls = logf(s);
        out[(size_t)r * CC + lane] = acc0 - m - ls;
        if (has1) out[(size_t)r * CC + 32 + lane] = acc1 - m - ls;
        __syncwarp();
    }
}

// ---------------- launch ----------------
extern "C" void kernel_launch(void* const* d_in, const int* in_sizes, int n_in,
                              void* d_out, int out_size)
{
    const float* x       = (const float*)d_in[0];
    const int*   ei      = (const int*)  d_in[1];
    const float* start_W = (const float*)d_in[2];
    const float* start_b = (const float*)d_in[3];
    const float* ln1_g   = (const float*)d_in[4];
    const float* ln1_b   = (const float*)d_in[5];
    const float* convW   = (const float*)d_in[6];
    const float* convB   = (const float*)d_in[7];
    const float* alpha_g = (const float*)d_in[8];
    const float* ln2_g   = (const float*)d_in[9];
    const float* ln2_b   = (const float*)d_in[10];
    const float* ffwW    = (const float*)d_in[11];
    const float* ffwB    = (const float*)d_in[12];
    const float* alpha_f = (const float*)d_in[13];
    const float* final_W = (const float*)d_in[14];
    const float* final_b = (const float*)d_in[15];
    float* out = (float*)d_out;

    float *h, *dinv;
    __nv_bfloat16 *c2b, *aggb, *wb, *w0hi, *w0lo;
    int *counts, *off, *cur, *eidx, *part;
    cudaGetSymbolAddress((void**)&h,      g_h);
    cudaGetSymbolAddress((void**)&c2b,    g_c2b);
    cudaGetSymbolAddress((void**)&aggb,   g_aggb);
    cudaGetSymbolAddress((void**)&wb,     g_wb);
    cudaGetSymbolAddress((void**)&w0hi,   g_w0hi);
    cudaGetSymbolAddress((void**)&w0lo,   g_w0lo);
    cudaGetSymbolAddress((void**)&dinv,   g_dinv);
    cudaGetSymbolAddress((void**)&counts, g_counts);
    cudaGetSymbolAddress((void**)&off,    g_off);
    cudaGetSymbolAddress((void**)&cur,    g_cur);
    cudaGetSymbolAddress((void**)&eidx,   g_eidx);
    cudaGetSymbolAddress((void**)&part,   g_part);

    const int* rowi = ei;
    const int* coli = ei + NE;

    cudaFuncSetAttribute(gemm_bf16_kernel<0>, cudaFuncAttributeMaxDynamicSharedMemorySize, SM_M0);
    cudaFuncSetAttribute(gemm_bf16_kernel<1>, cudaFuncAttributeMaxDynamicSharedMemorySize, SM_M1);
    cudaFuncSetAttribute(gemm_bf16_kernel<2>, cudaFuncAttributeMaxDynamicSharedMemorySize, SM_M2);

    const int GB = (NN + 63) / 64;
    const int NW = DD * DD + 2 * NL * DD * DD;

    // Launch order keeps gemm_bf16<1> at capture slot #4.
    convert_w_kernel<<<(NW + 255) / 256, 256>>>(start_W, convW, ffwW, w0hi, w0lo, wb);   // 1
    gemm_bf16_kernel<0><<<GB, 256, SM_M0>>>(x, w0hi, w0lo, start_b,                       // 2
                                            nullptr, nullptr, nullptr, nullptr,
                                            nullptr, nullptr, h, nullptr);
    zero_counts_kernel<<<(NN + 255) / 256, 256>>>(counts);                                // 3
    gemm_bf16_kernel<1><<<GB, 256, SM_M1>>>(h, wb, nullptr, nullptr,                      // 4 (layer 0 conv)
                                            ln1_g, ln1_b, nullptr, nullptr,
                                            nullptr, nullptr, nullptr, c2b);
    count_kernel<<<(NE + 255) / 256, 256>>>(coli, counts);                                // 5
    dinv_kernel<<<(NN + 255) / 256, 256>>>(counts, dinv);                                 // 6
    scan_block_kernel<<<NB_SCAN, 1024>>>(counts, off, part);                              // 7
    scan_part_kernel<<<1, 32>>>(part, off);                                               // 8
    add_carry_kernel<<<(NN + 255) / 256, 256>>>(counts, off, part, cur);                  // 9
    fill_kernel<<<(NE + 255) / 256, 256>>>(rowi, coli, cur, eidx);                        // 10

    for (int i = 0; i < NL; i++) {
        if (i > 0) {
            gemm_bf16_kernel<1><<<GB, 256, SM_M1>>>(h, wb + (size_t)i * DD * DD, nullptr, nullptr,
                                                    ln1_g + i * DD, ln1_b + i * DD,
                                                    nullptr, nullptr, nullptr, nullptr,
                                                    nullptr, c2b);
        }
        gather_kernel<<<(NN + 7) / 8, 256>>>(off, eidx, dinv, c2b, aggb);
        gemm_bf16_kernel<2><<<GB, 256, SM_M2>>>(h, wb + (size_t)(NL + i) * DD * DD, nullptr,
                                                ffwB + i * DD,
                                                ln2_g + i * DD, ln2_b + i * DD,
                                                aggb, convB + i * DD,
                                                alpha_g + i, alpha_f + i, h, nullptr);
    }

    final_kernel<<<(NN + 31) / 32, 128>>>(h, final_W, final_b, out);
}

// round 8
// speedup vs baseline: 2.0271x; 1.0030x over previous
#include <cuda_runtime.h>
#include <cuda_bf16.h>
#include <math.h>

#define NN 100000
#define NE 1600000
#define DD 128
#define CC 40
#define NL 3
#define NB_SCAN 98   // ceil(NN/1024)

// Static device scratch (allocation-free rule)
__device__ float          g_h[(size_t)NN * DD];
__device__ __nv_bfloat16  g_c2b[(size_t)NN * DD];
__device__ __nv_bfloat16  g_aggb[(size_t)NN * DD];
__device__ __nv_bfloat16  g_wb[6 * DD * DD];     // layer weights bf16
__device__ __nv_bfloat16  g_w0hi[DD * DD];       // start_W split
__device__ __nv_bfloat16  g_w0lo[DD * DD];
__device__ float g_dinv[NN];
__device__ int   g_counts[NN];
__device__ int   g_off[NN + 1];
__device__ int   g_cur[NN];
__device__ int   g_eidx[NE];
__device__ int   g_part[128];

typedef unsigned long long u64;
typedef unsigned int u32;

__device__ __forceinline__ float siluf(float x) { return x / (1.0f + expf(-x)); }

__device__ __forceinline__ float warp_sum(float v) {
#pragma unroll
    for (int o = 16; o > 0; o >>= 1) v += __shfl_xor_sync(0xffffffffu, v, o);
    return v;
}

// bf16x4 load/store
__device__ __forceinline__ float4 ldb4(const __nv_bfloat16* p) {
    uint2 u = *(const uint2*)p;
    __nv_bfloat162 a = *reinterpret_cast<const __nv_bfloat162*>(&u.x);
    __nv_bfloat162 b = *reinterpret_cast<const __nv_bfloat162*>(&u.y);
    float2 fa = __bfloat1622float2(a);
    float2 fb = __bfloat1622float2(b);
    return make_float4(fa.x, fa.y, fb.x, fb.y);
}
__device__ __forceinline__ void stb4(__nv_bfloat16* p, float4 v) {
    __nv_bfloat162 a = __floats2bfloat162_rn(v.x, v.y);
    __nv_bfloat162 b = __floats2bfloat162_rn(v.z, v.w);
    uint2 u;
    u.x = *reinterpret_cast<u32*>(&a);
    u.y = *reinterpret_cast<u32*>(&b);
    *(uint2*)p = u;
}
__device__ __forceinline__ u32 pkbf2(float a, float b) {
    __nv_bfloat162 t = __floats2bfloat162_rn(a, b);
    return *reinterpret_cast<u32*>(&t);
}

// HMMA primitives
__device__ __forceinline__ void ldsm4(u32* f, u32 addr) {
    asm volatile("ldmatrix.sync.aligned.m8n8.x4.shared.b16 {%0,%1,%2,%3}, [%4];"
                 : "=r"(f[0]), "=r"(f[1]), "=r"(f[2]), "=r"(f[3]) : "r"(addr));
}
__device__ __forceinline__ void ldsm2t(u32* f, u32 addr) {
    asm volatile("ldmatrix.sync.aligned.m8n8.x2.trans.shared.b16 {%0,%1}, [%2];"
                 : "=r"(f[0]), "=r"(f[1]) : "r"(addr));
}
__device__ __forceinline__ void mma16816(float* c, const u32* a, const u32* b) {
    asm volatile("mma.sync.aligned.m16n8k16.row.col.f32.bf16.bf16.f32 "
                 "{%0,%1,%2,%3}, {%4,%5,%6,%7}, {%8,%9}, {%0,%1,%2,%3};"
                 : "+f"(c[0]), "+f"(c[1]), "+f"(c[2]), "+f"(c[3])
                 : "r"(a[0]), "r"(a[1]), "r"(a[2]), "r"(a[3]), "r"(b[0]), "r"(b[1]));
}

// ---------------- weight conversion (once per call) ----------------
__global__ void convert_w_kernel(const float* __restrict__ startW,
                                 const float* __restrict__ convW,
                                 const float* __restrict__ ffwW,
                                 __nv_bfloat16* __restrict__ w0hi,
                                 __nv_bfloat16* __restrict__ w0lo,
                                 __nv_bfloat16* __restrict__ wb) {
    const int i = blockIdx.x * blockDim.x + threadIdx.x;
    const int s = DD * DD;          // 16384
    const int per = NL * DD * DD;   // 49152
    if (i < s) {
        float v = startW[i];
        __nv_bfloat16 hi = __float2bfloat16(v);
        w0hi[i] = hi;
        w0lo[i] = __float2bfloat16(v - __bfloat162float(hi));
    } else if (i < s + per) {
        wb[i - s] = __float2bfloat16(convW[i - s]);
    } else if (i < s + 2 * per) {
        wb[i - s] = __float2bfloat16(ffwW[i - s - per]);
    }
}

// ---------------- CSR build ----------------
__global__ void zero_counts_kernel(int* __restrict__ counts) {
    int i = blockIdx.x * blockDim.x + threadIdx.x;
    if (i < NN) counts[i] = 0;
}
__global__ void count_kernel(const int* __restrict__ col, int* __restrict__ counts) {
    int e = blockIdx.x * blockDim.x + threadIdx.x;
    if (e < NE) atomicAdd(&counts[col[e]], 1);
}
__global__ void dinv_kernel(const int* __restrict__ counts, float* __restrict__ dinv) {
    int i = blockIdx.x * blockDim.x + threadIdx.x;
    if (i < NN) dinv[i] = rsqrtf((float)(counts[i] + 1));
}
__global__ void __launch_bounds__(1024) scan_block_kernel(const int* __restrict__ counts,
                                                          int* __restrict__ off,
                                                          int* __restrict__ part) {
    __shared__ int wsum[32];
    const int t = threadIdx.x, lane = t & 31, w = t >> 5;
    const int i = blockIdx.x * 1024 + t;
    const int v = (i < NN) ? counts[i] : 0;
    int x = v;
#pragma unroll
    for (int o = 1; o < 32; o <<= 1) { int y = __shfl_up_sync(0xffffffffu, x, o); if (lane >= o) x += y; }
    if (lane == 31) wsum[w] = x;
    __syncthreads();
    if (w == 0) {
        int y = wsum[lane];
#pragma unroll
        for (int o = 1; o < 32; o <<= 1) { int z = __shfl_up_sync(0xffffffffu, y, o); if (lane >= o) y += z; }
        wsum[lane] = y;
    }
    __syncthreads();
    const int incl = x + (w > 0 ? wsum[w - 1] : 0);
    if (i < NN) off[i + 1] = incl;
    if (t == 1023) part[blockIdx.x] = incl;
}
__global__ void scan_part_kernel(int* __restrict__ part, int* __restrict__ off) {
    const int lane = threadIdx.x;
    int carry = 0;
    for (int base = 0; base < 128; base += 32) {
        const int idx = base + lane;
        const int v = (idx < NB_SCAN) ? part[idx] : 0;
        int x = v;
#pragma unroll
        for (int o = 1; o < 32; o <<= 1) { int y = __shfl_up_sync(0xffffffffu, x, o); if (lane >= o) x += y; }
        if (idx < NB_SCAN) part[idx] = carry + x - v;
        carry += __shfl_sync(0xffffffffu, x, 31);
    }
    if (lane == 0) off[0] = 0;
}
__global__ void add_carry_kernel(const int* __restrict__ counts,
                                 int* __restrict__ off,
                                 const int* __restrict__ part,
                                 int* __restrict__ cur) {
    const int i = blockIdx.x * blockDim.x + threadIdx.x;
    if (i >= NN) return;
    const int o = off[i + 1] + part[i >> 10];
    off[i + 1] = o;
    cur[i] = o - counts[i];
}
__global__ void fill_kernel(const int* __restrict__ rowi, const int* __restrict__ coli,
                            int* __restrict__ cur, int* __restrict__ eidx) {
    int e = blockIdx.x * blockDim.x + threadIdx.x;
    if (e < NE) {
        int p = atomicAdd(&cur[coli[e]], 1);
        eidx[p] = rowi[e];
    }
}

// ---------------- unified HMMA GEMM (128 cols, 64-row tiles) ----------------
// MODE 0: outf = silu(x @ (Whi+Wlo) + bias)        split-bf16 (3 MMA groups)
// MODE 1: outb = bf16( LN(in) @ W )                direct fragment store
// MODE 2: h1 = in + ag*silu(agg+convB) (stashed in smem);
//         outf = af*silu(LN(h1) @ W + bias) + h1
//
// Shared layouts (dynamic):
//  MODE0: Whi[0,34816) Wlo[34816,69632) Ahi[69632,87040) Alo[87040,104448); C overlays Whi
//  MODE1: W[0,34816) A[34816,52224)
//  MODE2: W[0,34816) A[34816,52224) H1[52224,86016); C overlays W
#define LDAB 136
#define LDC  132
#define SM_M0 104448
#define SM_M1 52224
#define SM_M2 86016

template <int MODE>
__global__ void __launch_bounds__(256, 2) gemm_bf16_kernel(
    const float* __restrict__ in,
    const __nv_bfloat16* __restrict__ Whi,
    const __nv_bfloat16* __restrict__ Wlo,
    const float* __restrict__ bias,
    const float* __restrict__ lng,
    const float* __restrict__ lnb,
    const __nv_bfloat16* __restrict__ aggb,
    const float* __restrict__ convB,
    const float* __restrict__ alpha_g,
    const float* __restrict__ alpha_f,
    float* __restrict__ outf,
    __nv_bfloat16* __restrict__ outb)
{
    extern __shared__ __align__(16) char smem[];
    __nv_bfloat16* Wsh  = (__nv_bfloat16*)(smem);
    __nv_bfloat16* Wlos = (__nv_bfloat16*)(smem + 34816);
    __nv_bfloat16* Ash  = (__nv_bfloat16*)(smem + (MODE == 0 ? 69632 : 34816));
    __nv_bfloat16* Alos = (__nv_bfloat16*)(smem + 87040);
    float*         H1sh = (float*)(smem + 52224);
    float*         Csh  = (float*)(smem);  // overlay (MODE 0/2 only, after sync)

    const int tid  = threadIdx.x;
    const int wid  = tid >> 5;
    const int lane = tid & 31;
    const int row0 = blockIdx.x * 64;

    float ag = 0.f;
    if (MODE == 2) ag = __ldg(alpha_g);

    // ---- W tile(s) to shared ----
    {
        const int r = tid >> 1, half = tid & 1;
        const uint4* src = (const uint4*)(Whi + (size_t)r * DD + half * 64);
        uint4* dst = (uint4*)(Wsh + r * LDAB + half * 64);
#pragma unroll
        for (int j = 0; j < 8; j++) dst[j] = src[j];
        if (MODE == 0) {
            const uint4* s2 = (const uint4*)(Wlo + (size_t)r * DD + half * 64);
            uint4* d2 = (uint4*)(Wlos + r * LDAB + half * 64);
#pragma unroll
            for (int j = 0; j < 8; j++) d2[j] = s2[j];
        }
    }

    // ---- prologue: build A tile(s) ----
    {
        float4 g4 = make_float4(0.f, 0.f, 0.f, 0.f);
        float4 b4 = make_float4(0.f, 0.f, 0.f, 0.f);
        float4 cb4 = make_float4(0.f, 0.f, 0.f, 0.f);
        if (MODE >= 1) {
            g4 = *(const float4*)(lng + lane * 4);
            b4 = *(const float4*)(lnb + lane * 4);
        }
        if (MODE == 2) cb4 = *(const float4*)(convB + lane * 4);
#pragma unroll
        for (int i = 0; i < 8; i++) {
            const int lr = wid * 8 + i;
            const int r  = row0 + lr;
            float4 v = make_float4(0.f, 0.f, 0.f, 0.f);
            if (r < NN) v = *(const float4*)(in + (size_t)r * DD + lane * 4);
            if (MODE == 0) {
                // split bf16: hi + lo
                __nv_bfloat16 hx = __float2bfloat16(v.x), hy = __float2bfloat16(v.y);
                __nv_bfloat16 hz = __float2bfloat16(v.z), hw = __float2bfloat16(v.w);
                uint2 phi;
                phi.x = pkbf2(__bfloat162float(hx), __bfloat162float(hy));
                phi.y = pkbf2(__bfloat162float(hz), __bfloat162float(hw));
                *(uint2*)(Ash + lr * LDAB + lane * 4) = phi;
                uint2 plo;
                plo.x = pkbf2(v.x - __bfloat162float(hx), v.y - __bfloat162float(hy));
                plo.y = pkbf2(v.z - __bfloat162float(hz), v.w - __bfloat162float(hw));
                *(uint2*)(Alos + lr * LDAB + lane * 4) = plo;
                continue;
            }
            if (MODE == 2) {
                float4 av = make_float4(0.f, 0.f, 0.f, 0.f);
                if (r < NN) av = ldb4(aggb + (size_t)r * DD + lane * 4);
                v.x = fmaf(ag, siluf(av.x + cb4.x), v.x);
                v.y = fmaf(ag, siluf(av.y + cb4.y), v.y);
                v.z = fmaf(ag, siluf(av.z + cb4.z), v.z);
                v.w = fmaf(ag, siluf(av.w + cb4.w), v.w);
                *(float4*)(H1sh + lr * LDC + lane * 4) = v;   // stash raw h1
            }
            float s1 = warp_sum(v.x + v.y + v.z + v.w);
            float s2 = warp_sum(v.x * v.x + v.y * v.y + v.z * v.z + v.w * v.w);
            float mu  = s1 * (1.0f / 128.0f);
            float var = fmaxf(s2 * (1.0f / 128.0f) - mu * mu, 0.0f);
            float rs  = rsqrtf(var + 1e-5f);
            uint2 p;
            p.x = pkbf2((v.x - mu) * rs * g4.x + b4.x, (v.y - mu) * rs * g4.y + b4.y);
            p.y = pkbf2((v.z - mu) * rs * g4.z + b4.z, (v.w - mu) * rs * g4.w + b4.w);
            *(uint2*)(Ash + lr * LDAB + lane * 4) = p;
        }
    }
    __syncthreads();

    // ---- HMMA mainloop: warp grid 2x4, warp tile 32x32 ----
    const int m0 = (wid >> 2) * 32;
    const int n0 = (wid & 3) * 32;
    const u32 a_base  = (u32)__cvta_generic_to_shared(Ash);
    const u32 al_base = (u32)__cvta_generic_to_shared(Alos);
    const u32 w_base  = (u32)__cvta_generic_to_shared(Wsh);
    const u32 wl_base = (u32)__cvta_generic_to_shared(Wlos);

    const int a_i   = lane & 7;
    const int a_sel = lane >> 3;
    const int a_row = ((a_sel & 1) ? 8 : 0) + a_i;
    const int a_kof = (a_sel & 2) ? 8 : 0;
    const int b_row = lane & 15;

    float acc[2][4][4];
#pragma unroll
    for (int mt = 0; mt < 2; mt++)
#pragma unroll
        for (int nt = 0; nt < 4; nt++)
#pragma unroll
            for (int q = 0; q < 4; q++) acc[mt][nt][q] = 0.f;

    if (MODE == 0) {
        // split: 3 MMA groups per k-step, single-buffered (24 mmas hide ldsm latency)
#pragma unroll
        for (int k0 = 0; k0 < DD; k0 += 16) {
            u32 ah[2][4], al[2][4], bh[4][2], bl[4][2];
#pragma unroll
            for (int mt = 0; mt < 2; mt++) {
                const u32 off = (u32)((m0 + mt * 16 + a_row) * (LDAB * 2) + (k0 + a_kof) * 2);
                ldsm4(ah[mt], a_base + off);
                ldsm4(al[mt], al_base + off);
            }
#pragma unroll
            for (int nt = 0; nt < 4; nt++) {
                const u32 off = (u32)((k0 + b_row) * (LDAB * 2) + (n0 + nt * 8) * 2);
                ldsm2t(bh[nt], w_base + off);
                ldsm2t(bl[nt], wl_base + off);
            }
#pragma unroll
            for (int mt = 0; mt < 2; mt++)
#pragma unroll
                for (int nt = 0; nt < 4; nt++) {
                    mma16816(acc[mt][nt], ah[mt], bh[nt]);
                    mma16816(acc[mt][nt], ah[mt], bl[nt]);
                    mma16816(acc[mt][nt], al[mt], bh[nt]);
                }
        }
    } else {
        // double-buffered software pipeline
        u32 af[2][2][4], bf[2][4][2];
#pragma unroll
        for (int mt = 0; mt < 2; mt++)
            ldsm4(af[0][mt], a_base + (u32)((m0 + mt * 16 + a_row) * (LDAB * 2) + a_kof * 2));
#pragma unroll
        for (int nt = 0; nt < 4; nt++)
            ldsm2t(bf[0][nt], w_base + (u32)(b_row * (LDAB * 2) + (n0 + nt * 8) * 2));
#pragma unroll
        for (int ks = 0; ks < 8; ks++) {
            const int cur = ks & 1;
            if (ks < 7) {
                const int k1 = (ks + 1) * 16;
#pragma unroll
                for (int mt = 0; mt < 2; mt++)
                    ldsm4(af[cur ^ 1][mt], a_base + (u32)((m0 + mt * 16 + a_row) * (LDAB * 2) + (k1 + a_kof) * 2));
#pragma unroll
                for (int nt = 0; nt < 4; nt++)
                    ldsm2t(bf[cur ^ 1][nt], w_base + (u32)((k1 + b_row) * (LDAB * 2) + (n0 + nt * 8) * 2));
            }
#pragma unroll
            for (int mt = 0; mt < 2; mt++)
#pragma unroll
                for (int nt = 0; nt < 4; nt++)
                    mma16816(acc[mt][nt], af[cur][mt], bf[cur][nt]);
        }
    }

    // ---- epilogue ----
    if (MODE == 1) {
        // direct bf16 fragment store (no staging, no extra barrier)
        const int g = lane >> 2, t = lane & 3;
#pragma unroll
        for (int mt = 0; mt < 2; mt++)
#pragma unroll
            for (int nt = 0; nt < 4; nt++) {
                const int col = n0 + nt * 8 + 2 * t;
                const int r0 = row0 + m0 + mt * 16 + g;
                const int r1 = r0 + 8;
                if (r0 < NN) *(u32*)(outb + (size_t)r0 * DD + col) = pkbf2(acc[mt][nt][0], acc[mt][nt][1]);
                if (r1 < NN) *(u32*)(outb + (size_t)r1 * DD + col) = pkbf2(acc[mt][nt][2], acc[mt][nt][3]);
            }
        return;
    }

    // MODE 0 / 2: stage C in shared (overlay W region) for coalesced fp32 epilogue
    __syncthreads();   // all warps done reading Wsh
    {
        const int g = lane >> 2, t = lane & 3;
#pragma unroll
        for (int mt = 0; mt < 2; mt++)
#pragma unroll
            for (int nt = 0; nt < 4; nt++) {
                const int row = m0 + mt * 16 + g;
                const int col = n0 + nt * 8 + 2 * t;
                *(float2*)(Csh + row * LDC + col)       = make_float2(acc[mt][nt][0], acc[mt][nt][1]);
                *(float2*)(Csh + (row + 8) * LDC + col) = make_float2(acc[mt][nt][2], acc[mt][nt][3]);
            }
    }
    __syncthreads();

    const float4 bias4 = *(const float4*)(bias + lane * 4);
    float af2 = 0.f;
    if (MODE == 2) af2 = __ldg(alpha_f);

#pragma unroll
    for (int i = 0; i < 8; i++) {
        const int lr = wid * 8 + i;
        const int r = row0 + lr;
        if (r >= NN) continue;
        float4 o = *(const float4*)(Csh + lr * LDC + lane * 4);
        if (MODE == 0) {
            o.x = siluf(o.x + bias4.x);
            o.y = siluf(o.y + bias4.y);
            o.z = siluf(o.z + bias4.z);
            o.w = siluf(o.w + bias4.w);
        } else {
            const float4 h1 = *(const float4*)(H1sh + lr * LDC + lane * 4);
            o.x = fmaf(af2, siluf(o.x + bias4.x), h1.x);
            o.y = fmaf(af2, siluf(o.y + bias4.y), h1.y);
            o.z = fmaf(af2, siluf(o.z + bias4.z), h1.z);
            o.w = fmaf(af2, siluf(o.w + bias4.w), h1.w);
        }
        *(float4*)(outf + (size_t)r * DD + lane * 4) = o;
    }
}

// ---------------- CSR gather: warp per node ----------------
__global__ void __launch_bounds__(256) gather_kernel(
    const int* __restrict__ off, const int* __restrict__ eidx,
    const float* __restrict__ dinv, const __nv_bfloat16* __restrict__ c2b,
    __nv_bfloat16* __restrict__ aggb)
{
    const int n = blockIdx.x * 8 + (threadIdx.x >> 5);
    if (n >= NN) return;
    const int lane = threadIdx.x & 31;
    const int s = __ldg(off + n);
    const int e = __ldg(off + n + 1);
    const float dn = __ldg(dinv + n);

    float4 acc = ldb4(c2b + (size_t)n * DD + lane * 4);
    acc.x *= dn; acc.y *= dn; acc.z *= dn; acc.w *= dn;
    for (int j0 = s; j0 < e; j0 += 32) {
        const int jn = min(32, e - j0);
        int eid = 0; float wv = 0.f;
        if (lane < jn) {
            eid = __ldg(eidx + j0 + lane);
            wv  = __ldg(dinv + eid);
        }
        int t = 0;
        for (; t + 4 <= jn; t += 4) {
            const int r0 = __shfl_sync(0xffffffffu, eid, t);
            const int r1 = __shfl_sync(0xffffffffu, eid, t + 1);
            const int r2 = __shfl_sync(0xffffffffu, eid, t + 2);
            const int r3 = __shfl_sync(0xffffffffu, eid, t + 3);
            const float w0 = __shfl_sync(0xffffffffu, wv, t);
            const float w1 = __shfl_sync(0xffffffffu, wv, t + 1);
            const float w2 = __shfl_sync(0xffffffffu, wv, t + 2);
            const float w3 = __shfl_sync(0xffffffffu, wv, t + 3);
            const float4 v0 = ldb4(c2b + (size_t)r0 * DD + lane * 4);
            const float4 v1 = ldb4(c2b + (size_t)r1 * DD + lane * 4);
            const float4 v2 = ldb4(c2b + (size_t)r2 * DD + lane * 4);
            const float4 v3 = ldb4(c2b + (size_t)r3 * DD + lane * 4);
            acc.x += w0 * v0.x + w1 * v1.x + w2 * v2.x + w3 * v3.x;
            acc.y += w0 * v0.y + w1 * v1.y + w2 * v2.y + w3 * v3.y;
            acc.z += w0 * v0.z + w1 * v1.z + w2 * v2.z + w3 * v3.z;
            acc.w += w0 * v0.w + w1 * v1.w + w2 * v2.w + w3 * v3.w;
        }
        for (; t < jn; t++) {
            const int r = __shfl_sync(0xffffffffu, eid, t);
            const float w = __shfl_sync(0xffffffffu, wv, t);
            const float4 v = ldb4(c2b + (size_t)r * DD + lane * 4);
            acc.x += w * v.x; acc.y += w * v.y; acc.z += w * v.z; acc.w += w * v.w;
        }
    }
    acc.x *= dn; acc.y *= dn; acc.z *= dn; acc.w *= dn;
    stb4(aggb + (size_t)n * DD + lane * 4, acc);
}

// ---------------- final: logits (128x40) + log_softmax ----------------
__global__ void __launch_bounds__(128) final_kernel(
    const float* __restrict__ h, const float* __restrict__ Wf,
    const float* __restrict__ fb, float* __restrict__ out)
{
    __shared__ float Wsh[DD * CC];
    __shared__ float bsh[CC];
    __shared__ float rowbuf[4][DD];
    const int tid = threadIdx.x;
    for (int i = tid; i < DD * CC; i += 128) Wsh[i] = Wf[i];
    if (tid < CC) bsh[tid] = fb[tid];
    __syncthreads();

    const int wid = tid >> 5, lane = tid & 31;
    const int rbase = blockIdx.x * 32 + wid * 8;
    const bool has1 = (lane < CC - 32);

    for (int ri = 0; ri < 8; ri++) {
        const int r = rbase + ri;
        if (r >= NN) return;
        float4 v = *(const float4*)(h + (size_t)r * DD + lane * 4);
        *(float4*)(&rowbuf[wid][lane * 4]) = v;
        __syncwarp();

        float acc0 = bsh[lane];
        float acc1 = has1 ? bsh[32 + lane] : 0.f;
#pragma unroll 4
        for (int k = 0; k < DD; k++) {
            float hv = rowbuf[wid][k];
            acc0 = fmaf(hv, Wsh[k * CC + lane], acc0);
            if (has1) acc1 = fmaf(hv, Wsh[k * CC + 32 + lane], acc1);
        }
        float m = has1 ? fmaxf(acc0, acc1) : acc0;
#pragma unroll
        for (int o = 16; o > 0; o >>= 1) m = fmaxf(m, __shfl_xor_sync(0xffffffffu, m, o));
        float s = expf(acc0 - m) + (has1 ? expf(acc1 - m) : 0.f);
#pragma unroll
        for (int o = 16; o > 0; o >>= 1) s += __shfl_xor_sync(0xffffffffu, s, o);
        const float ls = logf(s);
        out[(size_t)r * CC + lane] = acc0 - m - ls;
        if (has1) out[(size_t)r * CC + 32 + lane] = acc1 - m - ls;
        __syncwarp();
    }
}

// ---------------- launch ----------------
extern "C" void kernel_launch(void* const* d_in, const int* in_sizes, int n_in,
                              void* d_out, int out_size)
{
    const float* x       = (const float*)d_in[0];
    const int*   ei      = (const int*)  d_in[1];
    const float* start_W = (const float*)d_in[2];
    const float* start_b = (const float*)d_in[3];
    const float* ln1_g   = (const float*)d_in[4];
    const float* ln1_b   = (const float*)d_in[5];
    const float* convW   = (const float*)d_in[6];
    const float* convB   = (const float*)d_in[7];
    const float* alpha_g = (const float*)d_in[8];
    const float* ln2_g   = (const float*)d_in[9];
    const float* ln2_b   = (const float*)d_in[10];
    const float* ffwW    = (const float*)d_in[11];
    const float* ffwB    = (const float*)d_in[12];
    const float* alpha_f = (const float*)d_in[13];
    const float* final_W = (const float*)d_in[14];
    const float* final_b = (const float*)d_in[15];
    float* out = (float*)d_out;

    float *h, *dinv;
    __nv_bfloat16 *c2b, *aggb, *wb, *w0hi, *w0lo;
    int *counts, *off, *cur, *eidx, *part;
    cudaGetSymbolAddress((void**)&h,      g_h);
    cudaGetSymbolAddress((void**)&c2b,    g_c2b);
    cudaGetSymbolAddress((void**)&aggb,   g_aggb);
    cudaGetSymbolAddress((void**)&wb,     g_wb);
    cudaGetSymbolAddress((void**)&w0hi,   g_w0hi);
    cudaGetSymbolAddress((void**)&w0lo,   g_w0lo);
    cudaGetSymbolAddress((void**)&dinv,   g_dinv);
    cudaGetSymbolAddress((void**)&counts, g_counts);
    cudaGetSymbolAddress((void**)&off,    g_off);
    cudaGetSymbolAddress((void**)&cur,    g_cur);
    cudaGetSymbolAddress((void**)&eidx,   g_eidx);
    cudaGetSymbolAddress((void**)&part,   g_part);

    const int* rowi = ei;
    const int* coli = ei + NE;

    cudaFuncSetAttribute(gemm_bf16_kernel<0>, cudaFuncAttributeMaxDynamicSharedMemorySize, SM_M0);
    cudaFuncSetAttribute(gemm_bf16_kernel<1>, cudaFuncAttributeMaxDynamicSharedMemorySize, SM_M1);
    cudaFuncSetAttribute(gemm_bf16_kernel<2>, cudaFuncAttributeMaxDynamicSharedMemorySize, SM_M2);

    const int GB = (NN + 63) / 64;
    const int NW = DD * DD + 2 * NL * DD * DD;

    // Launch order keeps gemm_bf16<1> at capture slot #4.
    convert_w_kernel<<<(NW + 255) / 256, 256>>>(start_W, convW, ffwW, w0hi, w0lo, wb);   // 1
    gemm_bf16_kernel<0><<<GB, 256, SM_M0>>>(x, w0hi, w0lo, start_b,                       // 2
                                            nullptr, nullptr, nullptr, nullptr,
                                            nullptr, nullptr, h, nullptr);
    zero_counts_kernel<<<(NN + 255) / 256, 256>>>(counts);                                // 3
    gemm_bf16_kernel<1><<<GB, 256, SM_M1>>>(h, wb, nullptr, nullptr,                      // 4 (layer 0 conv)
                                            ln1_g, ln1_b, nullptr, nullptr,
                                            nullptr, nullptr, nullptr, c2b);
    count_kernel<<<(NE + 255) / 256, 256>>>(coli, counts);                                // 5
    dinv_kernel<<<(NN + 255) / 256, 256>>>(counts, dinv);                                 // 6
    scan_block_kernel<<<NB_SCAN, 1024>>>(counts, off, part);                              // 7
    scan_part_kernel<<<1, 32>>>(part, off);                                               // 8
    add_carry_kernel<<<(NN + 255) / 256, 256>>>(counts, off, part, cur);                  // 9
    fill_kernel<<<(NE + 255) / 256, 256>>>(rowi, coli, cur, eidx);                        // 10

    for (int i = 0; i < NL; i++) {
        if (i > 0) {
            gemm_bf16_kernel<1><<<GB, 256, SM_M1>>>(h, wb + (size_t)i * DD * DD, nullptr, nullptr,
                                                    ln1_g + i * DD, ln1_b + i * DD,
                                                    nullptr, nullptr, nullptr, nullptr,
                                                    nullptr, c2b);
        }
        gather_kernel<<<(NN + 7) / 8, 256>>>(off, eidx, dinv, c2b, aggb);
        gemm_bf16_kernel<2><<<GB, 256, SM_M2>>>(h, wb + (size_t)(NL + i) * DD * DD, nullptr,
                                                ffwB + i * DD,
                                                ln2_g + i * DD, ln2_b + i * DD,
                                                aggb, convB + i * DD,
                                                alpha_g + i, alpha_f + i, h, nullptr);
    }

    final_kernel<<<(NN + 31) / 32, 128>>>(h, final_W, final_b, out);
}

// round 10
// speedup vs baseline: 2.0489x; 1.0108x over previous
#include <cuda_runtime.h>
#include <cuda_bf16.h>
#include <math.h>

#define NN 100000
#define NE 1600000
#define DD 128
#define CC 40
#define NL 3
#define NB_SCAN 98

__device__ float          g_h[(size_t)NN * DD];
__device__ __nv_bfloat16  g_c2b[(size_t)NN * DD];
__device__ __nv_bfloat16  g_aggb[(size_t)NN * DD];
__device__ __nv_bfloat16  g_wb[6 * DD * DD];
__device__ __nv_bfloat16  g_w0hi[DD * DD];
__device__ __nv_bfloat16  g_w0lo[DD * DD];
__device__ float g_dinv[NN];
__device__ int g_counts[NN], g_off[NN + 1], g_cur[NN], g_eidx[NE], g_part[128];

typedef unsigned long long u64;
typedef unsigned int u32;

__device__ __forceinline__ float siluf(float x) { return x / (1.0f + expf(-x)); }

__device__ __forceinline__ float warp_sum(float v) {
#pragma unroll
    for (int o = 16; o > 0; o >>= 1) v += __shfl_xor_sync(0xffffffffu, v, o);
    return v;
}
__device__ __forceinline__ float4 ldb4(const __nv_bfloat16* p) {
    uint2 u = *(const uint2*)p;
    __nv_bfloat162 a = *reinterpret_cast<const __nv_bfloat162*>(&u.x);
    __nv_bfloat162 b = *reinterpret_cast<const __nv_bfloat162*>(&u.y);
    float2 fa = __bfloat1622float2(a), fb = __bfloat1622float2(b);
    return make_float4(fa.x, fa.y, fb.x, fb.y);
}
__device__ __forceinline__ void stb4(__nv_bfloat16* p, float4 v) {
    __nv_bfloat162 a = __floats2bfloat162_rn(v.x, v.y), b = __floats2bfloat162_rn(v.z, v.w);
    uint2 u; u.x = *reinterpret_cast<u32*>(&a); u.y = *reinterpret_cast<u32*>(&b);
    *(uint2*)p = u;
}
__device__ __forceinline__ u32 pkbf2(float a, float b) {
    __nv_bfloat162 t = __floats2bfloat162_rn(a, b);
    return *reinterpret_cast<u32*>(&t);
}
__device__ __forceinline__ void ldsm4(u32* f, u32 addr) {
    asm volatile("ldmatrix.sync.aligned.m8n8.x4.shared.b16 {%0,%1,%2,%3}, [%4];"
                 : "=r"(f[0]), "=r"(f[1]), "=r"(f[2]), "=r"(f[3]) : "r"(addr));
}
__device__ __forceinline__ void ldsm2t(u32* f, u32 addr) {
    asm volatile("ldmatrix.sync.aligned.m8n8.x2.trans.shared.b16 {%0,%1}, [%2];"
                 : "=r"(f[0]), "=r"(f[1]) : "r"(addr));
}
__device__ __forceinline__ void mma16816(float* c, const u32* a, const u32* b) {
    asm volatile("mma.sync.aligned.m16n8k16.row.col.f32.bf16.bf16.f32 "
                 "{%0,%1,%2,%3}, {%4,%5,%6,%7}, {%8,%9}, {%0,%1,%2,%3};"
                 : "+f"(c[0]), "+f"(c[1]), "+f"(c[2]), "+f"(c[3])
                 : "r"(a[0]), "r"(a[1]), "r"(a[2]), "r"(a[3]), "r"(b[0]), "r"(b[1]));
}

// ---------------- weight conversion ----------------
__global__ void convert_w_kernel(const float* __restrict__ startW,
                                 const float* __restrict__ convW,
                                 const float* __restrict__ ffwW,
                                 __nv_bfloat16* __restrict__ w0hi,
                                 __nv_bfloat16* __restrict__ w0lo,
                                 __nv_bfloat16* __restrict__ wb) {
    const int i = blockIdx.x * blockDim.x + threadIdx.x;
    const int s = DD * DD, per = NL * DD * DD;
    if (i < s) {
        float v = startW[i];
        __nv_bfloat16 hi = __float2bfloat16(v);
        w0hi[i] = hi;
        w0lo[i] = __float2bfloat16(v - __bfloat162float(hi));
    } else if (i < s + per) {
        wb[i - s] = __float2bfloat16(convW[i - s]);
    } else if (i < s + 2 * per) {
        wb[i - s] = __float2bfloat16(ffwW[i - s - per]);
    }
}

// ---------------- CSR build ----------------
__global__ void zero_counts_kernel(int* c) { int i = blockIdx.x * blockDim.x + threadIdx.x; if (i < NN) c[i] = 0; }
__global__ void count_kernel(const int* __restrict__ col, int* __restrict__ c) {
    int e = blockIdx.x * blockDim.x + threadIdx.x; if (e < NE) atomicAdd(&c[col[e]], 1);
}
__global__ void dinv_kernel(const int* __restrict__ c, float* __restrict__ d) {
    int i = blockIdx.x * blockDim.x + threadIdx.x; if (i < NN) d[i] = rsqrtf((float)(c[i] + 1));
}
__global__ void __launch_bounds__(1024) scan_block_kernel(const int* __restrict__ counts,
                                                          int* __restrict__ off, int* __restrict__ part) {
    __shared__ int wsum[32];
    const int t = threadIdx.x, lane = t & 31, w = t >> 5;
    const int i = blockIdx.x * 1024 + t;
    const int v = (i < NN) ? counts[i] : 0;
    int x = v;
#pragma unroll
    for (int o = 1; o < 32; o <<= 1) { int y = __shfl_up_sync(0xffffffffu, x, o); if (lane >= o) x += y; }
    if (lane == 31) wsum[w] = x;
    __syncthreads();
    if (w == 0) {
        int y = wsum[lane];
#pragma unroll
        for (int o = 1; o < 32; o <<= 1) { int z = __shfl_up_sync(0xffffffffu, y, o); if (lane >= o) y += z; }
        wsum[lane] = y;
    }
    __syncthreads();
    const int incl = x + (w > 0 ? wsum[w - 1] : 0);
    if (i < NN) off[i + 1] = incl;
    if (t == 1023) part[blockIdx.x] = incl;
}
__global__ void scan_part_kernel(int* __restrict__ part, int* __restrict__ off) {
    const int lane = threadIdx.x;
    int carry = 0;
    for (int base = 0; base < 128; base += 32) {
        const int idx = base + lane;
        const int v = (idx < NB_SCAN) ? part[idx] : 0;
        int x = v;
#pragma unroll
        for (int o = 1; o < 32; o <<= 1) { int y = __shfl_up_sync(0xffffffffu, x, o); if (lane >= o) x += y; }
        if (idx < NB_SCAN) part[idx] = carry + x - v;
        carry += __shfl_sync(0xffffffffu, x, 31);
    }
    if (lane == 0) off[0] = 0;
}
__global__ void add_carry_kernel(const int* __restrict__ counts, int* __restrict__ off,
                                 const int* __restrict__ part, int* __restrict__ cur) {
    const int i = blockIdx.x * blockDim.x + threadIdx.x;
    if (i >= NN) return;
    const int o = off[i + 1] + part[i >> 10];
    off[i + 1] = o; cur[i] = o - counts[i];
}
__global__ void fill_kernel(const int* __restrict__ rowi, const int* __restrict__ coli,
                            int* __restrict__ cur, int* __restrict__ eidx) {
    int e = blockIdx.x * blockDim.x + threadIdx.x;
    if (e < NE) { int p = atomicAdd(&cur[coli[e]], 1); eidx[p] = rowi[e]; }
}

// ---------------- conv GEMM: 128x128 block, 4m x 2n warp grid, 32x64 warp tile ----------------
// outb = bf16( LN(in) @ W );   direct fragment store; single-buffered ldsm (16 mma/group)
#define LDAB 136
#define SM_G1 69632

__global__ void __launch_bounds__(256, 2) gemm1_kernel(
    const float* __restrict__ in, const __nv_bfloat16* __restrict__ Wb,
    const float* __restrict__ lng, const float* __restrict__ lnb,
    __nv_bfloat16* __restrict__ outb)
{
    extern __shared__ __align__(16) char smem[];
    __nv_bfloat16* Wsh = (__nv_bfloat16*)(smem);
    __nv_bfloat16* Ash = (__nv_bfloat16*)(smem + 34816);
    const int tid = threadIdx.x, wid = tid >> 5, lane = tid & 31;
    const int row0 = blockIdx.x * 128;

    {   // W tile: 128 x 128 bf16
        const int r = tid >> 1, half = tid & 1;
        const uint4* src = (const uint4*)(Wb + (size_t)r * DD + half * 64);
        uint4* dst = (uint4*)(Wsh + r * LDAB + half * 64);
#pragma unroll
        for (int j = 0; j < 8; j++) dst[j] = src[j];
    }
    {   // A prologue: 16 rows per warp, LN per row
        const float4 g4 = *(const float4*)(lng + lane * 4);
        const float4 b4 = *(const float4*)(lnb + lane * 4);
#pragma unroll
        for (int i = 0; i < 16; i++) {
            const int lr = wid * 16 + i;
            const int r = row0 + lr;
            float4 v = (r < NN) ? *(const float4*)(in + (size_t)r * DD + lane * 4)
                                : make_float4(0.f, 0.f, 0.f, 0.f);
            float s1 = warp_sum(v.x + v.y + v.z + v.w);
            float s2 = warp_sum(v.x * v.x + v.y * v.y + v.z * v.z + v.w * v.w);
            float mu  = s1 * (1.0f / 128.0f);
            float var = fmaxf(s2 * (1.0f / 128.0f) - mu * mu, 0.0f);
            float rs  = rsqrtf(var + 1e-5f);
            uint2 p;
            p.x = pkbf2((v.x - mu) * rs * g4.x + b4.x, (v.y - mu) * rs * g4.y + b4.y);
            p.y = pkbf2((v.z - mu) * rs * g4.z + b4.z, (v.w - mu) * rs * g4.w + b4.w);
            *(uint2*)(Ash + lr * LDAB + lane * 4) = p;
        }
    }
    __syncthreads();

    const int m0 = (wid >> 1) * 32;     // 4 m-groups
    const int n0 = (wid & 1) * 64;      // 2 n-groups
    const u32 a_base = (u32)__cvta_generic_to_shared(Ash);
    const u32 w_base = (u32)__cvta_generic_to_shared(Wsh);
    const int a_i = lane & 7, a_sel = lane >> 3;
    const int a_row = ((a_sel & 1) ? 8 : 0) + a_i;
    const int a_kof = (a_sel & 2) ? 8 : 0;
    const int b_row = lane & 15;

    float acc[2][8][4];
#pragma unroll
    for (int mt = 0; mt < 2; mt++)
#pragma unroll
        for (int nt = 0; nt < 8; nt++)
#pragma unroll
            for (int q = 0; q < 4; q++) acc[mt][nt][q] = 0.f;

#pragma unroll
    for (int k0 = 0; k0 < DD; k0 += 16) {
        u32 af[2][4], bf[8][2];
#pragma unroll
        for (int mt = 0; mt < 2; mt++)
            ldsm4(af[mt], a_base + (u32)((m0 + mt * 16 + a_row) * (LDAB * 2) + (k0 + a_kof) * 2));
#pragma unroll
        for (int nt = 0; nt < 8; nt++)
            ldsm2t(bf[nt], w_base + (u32)((k0 + b_row) * (LDAB * 2) + (n0 + nt * 8) * 2));
#pragma unroll
        for (int mt = 0; mt < 2; mt++)
#pragma unroll
            for (int nt = 0; nt < 8; nt++)
                mma16816(acc[mt][nt], af[mt], bf[nt]);
    }

    // direct bf16 fragment store
    const int g = lane >> 2, t = lane & 3;
#pragma unroll
    for (int mt = 0; mt < 2; mt++) {
        const int r0 = row0 + m0 + mt * 16 + g;
        const int r1 = r0 + 8;
#pragma unroll
        for (int nt = 0; nt < 8; nt++) {
            const int col = n0 + nt * 8 + 2 * t;
            if (r0 < NN) *(u32*)(outb + (size_t)r0 * DD + col) = pkbf2(acc[mt][nt][0], acc[mt][nt][1]);
            if (r1 < NN) *(u32*)(outb + (size_t)r1 * DD + col) = pkbf2(acc[mt][nt][2], acc[mt][nt][3]);
        }
    }
}

// ---------------- unified HMMA GEMM (MODE 0 start / MODE 2 ffn) — proven R8 kernel ----------------
#define LDC  132
#define SM_M0 104448
#define SM_M2 86016

template <int MODE>
__global__ void __launch_bounds__(256, 2) gemm_bf16_kernel(
    const float* __restrict__ in,
    const __nv_bfloat16* __restrict__ Whi,
    const __nv_bfloat16* __restrict__ Wlo,
    const float* __restrict__ bias,
    const float* __restrict__ lng,
    const float* __restrict__ lnb,
    const __nv_bfloat16* __restrict__ aggb,
    const float* __restrict__ convB,
    const float* __restrict__ alpha_g,
    const float* __restrict__ alpha_f,
    float* __restrict__ outf)
{
    extern __shared__ __align__(16) char smem[];
    __nv_bfloat16* Wsh  = (__nv_bfloat16*)(smem);
    __nv_bfloat16* Wlos = (__nv_bfloat16*)(smem + 34816);
    __nv_bfloat16* Ash  = (__nv_bfloat16*)(smem + (MODE == 0 ? 69632 : 34816));
    __nv_bfloat16* Alos = (__nv_bfloat16*)(smem + 87040);
    float*         H1sh = (float*)(smem + 52224);
    float*         Csh  = (float*)(smem);

    const int tid = threadIdx.x, wid = tid >> 5, lane = tid & 31;
    const int row0 = blockIdx.x * 64;
    float ag = 0.f;
    if (MODE == 2) ag = __ldg(alpha_g);

    {
        const int r = tid >> 1, half = tid & 1;
        const uint4* src = (const uint4*)(Whi + (size_t)r * DD + half * 64);
        uint4* dst = (uint4*)(Wsh + r * LDAB + half * 64);
#pragma unroll
        for (int j = 0; j < 8; j++) dst[j] = src[j];
        if (MODE == 0) {
            const uint4* s2 = (const uint4*)(Wlo + (size_t)r * DD + half * 64);
            uint4* d2 = (uint4*)(Wlos + r * LDAB + half * 64);
#pragma unroll
            for (int j = 0; j < 8; j++) d2[j] = s2[j];
        }
    }
    {
        float4 g4 = make_float4(0.f, 0.f, 0.f, 0.f);
        float4 b4 = make_float4(0.f, 0.f, 0.f, 0.f);
        float4 cb4 = make_float4(0.f, 0.f, 0.f, 0.f);
        if (MODE == 2) {
            g4 = *(const float4*)(lng + lane * 4);
            b4 = *(const float4*)(lnb + lane * 4);
            cb4 = *(const float4*)(convB + lane * 4);
        }
#pragma unroll
        for (int i = 0; i < 8; i++) {
            const int lr = wid * 8 + i;
            const int r = row0 + lr;
            float4 v = make_float4(0.f, 0.f, 0.f, 0.f);
            if (r < NN) v = *(const float4*)(in + (size_t)r * DD + lane * 4);
            if (MODE == 0) {
                __nv_bfloat16 hx = __float2bfloat16(v.x), hy = __float2bfloat16(v.y);
                __nv_bfloat16 hz = __float2bfloat16(v.z), hw = __float2bfloat16(v.w);
                uint2 phi;
                phi.x = pkbf2(__bfloat162float(hx), __bfloat162float(hy));
                phi.y = pkbf2(__bfloat162float(hz), __bfloat162float(hw));
                *(uint2*)(Ash + lr * LDAB + lane * 4) = phi;
                uint2 plo;
                plo.x = pkbf2(v.x - __bfloat162float(hx), v.y - __bfloat162float(hy));
                plo.y = pkbf2(v.z - __bfloat162float(hz), v.w - __bfloat162float(hw));
                *(uint2*)(Alos + lr * LDAB + lane * 4) = plo;
                continue;
            }
            float4 av = make_float4(0.f, 0.f, 0.f, 0.f);
            if (r < NN) av = ldb4(aggb + (size_t)r * DD + lane * 4);
            v.x = fmaf(ag, siluf(av.x + cb4.x), v.x);
            v.y = fmaf(ag, siluf(av.y + cb4.y), v.y);
            v.z = fmaf(ag, siluf(av.z + cb4.z), v.z);
            v.w = fmaf(ag, siluf(av.w + cb4.w), v.w);
            *(float4*)(H1sh + lr * LDC + lane * 4) = v;
            float s1 = warp_sum(v.x + v.y + v.z + v.w);
            float s2 = warp_sum(v.x * v.x + v.y * v.y + v.z * v.z + v.w * v.w);
            float mu  = s1 * (1.0f / 128.0f);
            float var = fmaxf(s2 * (1.0f / 128.0f) - mu * mu, 0.0f);
            float rs  = rsqrtf(var + 1e-5f);
            uint2 p;
            p.x = pkbf2((v.x - mu) * rs * g4.x + b4.x, (v.y - mu) * rs * g4.y + b4.y);
            p.y = pkbf2((v.z - mu) * rs * g4.z + b4.z, (v.w - mu) * rs * g4.w + b4.w);
            *(uint2*)(Ash + lr * LDAB + lane * 4) = p;
        }
    }
    __syncthreads();

    const int m0 = (wid >> 2) * 32, n0 = (wid & 3) * 32;
    const u32 a_base  = (u32)__cvta_generic_to_shared(Ash);
    const u32 al_base = (u32)__cvta_generic_to_shared(Alos);
    const u32 w_base  = (u32)__cvta_generic_to_shared(Wsh);
    const u32 wl_base = (u32)__cvta_generic_to_shared(Wlos);
    const int a_i = lane & 7, a_sel = lane >> 3;
    const int a_row = ((a_sel & 1) ? 8 : 0) + a_i;
    const int a_kof = (a_sel & 2) ? 8 : 0;
    const int b_row = lane & 15;

    float acc[2][4][4];
#pragma unroll
    for (int mt = 0; mt < 2; mt++)
#pragma unroll
        for (int nt = 0; nt < 4; nt++)
#pragma unroll
            for (int q = 0; q < 4; q++) acc[mt][nt][q] = 0.f;

    if (MODE == 0) {
#pragma unroll
        for (int k0 = 0; k0 < DD; k0 += 16) {
            u32 ah[2][4], al[2][4], bh[4][2], bl[4][2];
#pragma unroll
            for (int mt = 0; mt < 2; mt++) {
                const u32 off = (u32)((m0 + mt * 16 + a_row) * (LDAB * 2) + (k0 + a_kof) * 2);
                ldsm4(ah[mt], a_base + off);
                ldsm4(al[mt], al_base + off);
            }
#pragma unroll
            for (int nt = 0; nt < 4; nt++) {
                const u32 off = (u32)((k0 + b_row) * (LDAB * 2) + (n0 + nt * 8) * 2);
                ldsm2t(bh[nt], w_base + off);
                ldsm2t(bl[nt], wl_base + off);
            }
#pragma unroll
            for (int mt = 0; mt < 2; mt++)
#pragma unroll
                for (int nt = 0; nt < 4; nt++) {
                    mma16816(acc[mt][nt], ah[mt], bh[nt]);
                    mma16816(acc[mt][nt], ah[mt], bl[nt]);
                    mma16816(acc[mt][nt], al[mt], bh[nt]);
                }
        }
    } else {
        u32 af[2][2][4], bf[2][4][2];
#pragma unroll
        for (int mt = 0; mt < 2; mt++)
            ldsm4(af[0][mt], a_base + (u32)((m0 + mt * 16 + a_row) * (LDAB * 2) + a_kof * 2));
#pragma unroll
        for (int nt = 0; nt < 4; nt++)
            ldsm2t(bf[0][nt], w_base + (u32)(b_row * (LDAB * 2) + (n0 + nt * 8) * 2));
#pragma unroll
        for (int ks = 0; ks < 8; ks++) {
            const int cur = ks & 1;
            if (ks < 7) {
                const int k1 = (ks + 1) * 16;
#pragma unroll
                for (int mt = 0; mt < 2; mt++)
                    ldsm4(af[cur ^ 1][mt], a_base + (u32)((m0 + mt * 16 + a_row) * (LDAB * 2) + (k1 + a_kof) * 2));
#pragma unroll
                for (int nt = 0; nt < 4; nt++)
                    ldsm2t(bf[cur ^ 1][nt], w_base + (u32)((k1 + b_row) * (LDAB * 2) + (n0 + nt * 8) * 2));
            }
#pragma unroll
            for (int mt = 0; mt < 2; mt++)
#pragma unroll
                for (int nt = 0; nt < 4; nt++)
                    mma16816(acc[mt][nt], af[cur][mt], bf[cur][nt]);
        }
    }

    __syncthreads();
    {
        const int g = lane >> 2, t = lane & 3;
#pragma unroll
        for (int mt = 0; mt < 2; mt++)
#pragma unroll
            for (int nt = 0; nt < 4; nt++) {
                const int row = m0 + mt * 16 + g;
                const int col = n0 + nt * 8 + 2 * t;
                *(float2*)(Csh + row * LDC + col)       = make_float2(acc[mt][nt][0], acc[mt][nt][1]);
                *(float2*)(Csh + (row + 8) * LDC + col) = make_float2(acc[mt][nt][2], acc[mt][nt][3]);
            }
    }
    __syncthreads();

    const float4 bias4 = *(const float4*)(bias + lane * 4);
    float af2 = 0.f;
    if (MODE == 2) af2 = __ldg(alpha_f);

#pragma unroll
    for (int i = 0; i < 8; i++) {
        const int lr = wid * 8 + i;
        const int r = row0 + lr;
        if (r >= NN) continue;
        float4 o = *(const float4*)(Csh + lr * LDC + lane * 4);
        if (MODE == 0) {
            o.x = siluf(o.x + bias4.x);
            o.y = siluf(o.y + bias4.y);
            o.z = siluf(o.z + bias4.z);
            o.w = siluf(o.w + bias4.w);
        } else {
            const float4 h1 = *(const float4*)(H1sh + lr * LDC + lane * 4);
            o.x = fmaf(af2, siluf(o.x + bias4.x), h1.x);
            o.y = fmaf(af2, siluf(o.y + bias4.y), h1.y);
            o.z = fmaf(af2, siluf(o.z + bias4.z), h1.z);
            o.w = fmaf(af2, siluf(o.w + bias4.w), h1.w);
        }
        *(float4*)(outf + (size_t)r * DD + lane * 4) = o;
    }
}

// ---------------- CSR gather: warp per node, 8-way unrolled ----------------
__global__ void __launch_bounds__(256) gather_kernel(
    const int* __restrict__ off, const int* __restrict__ eidx,
    const float* __restrict__ dinv, const __nv_bfloat16* __restrict__ c2b,
    __nv_bfloat16* __restrict__ aggb)
{
    const int n = blockIdx.x * 8 + (threadIdx.x >> 5);
    if (n >= NN) return;
    const int lane = threadIdx.x & 31;
    const int s = __ldg(off + n), e = __ldg(off + n + 1);
    const float dn = __ldg(dinv + n);

    float4 acc = ldb4(c2b + (size_t)n * DD + lane * 4);
    acc.x *= dn; acc.y *= dn; acc.z *= dn; acc.w *= dn;
    for (int j0 = s; j0 < e; j0 += 32) {
        const int jn = min(32, e - j0);
        int eid = 0; float wv = 0.f;
        if (lane < jn) { eid = __ldg(eidx + j0 + lane); wv = __ldg(dinv + eid); }
        int t = 0;
        for (; t + 8 <= jn; t += 8) {
            int rr[8]; float ww[8]; float4 vv[8];
#pragma unroll
            for (int q = 0; q < 8; q++) {
                rr[q] = __shfl_sync(0xffffffffu, eid, t + q);
                ww[q] = __shfl_sync(0xffffffffu, wv, t + q);
            }
#pragma unroll
            for (int q = 0; q < 8; q++)
                vv[q] = ldb4(c2b + (size_t)rr[q] * DD + lane * 4);
#pragma unroll
            for (int q = 0; q < 8; q++) {
                acc.x = fmaf(ww[q], vv[q].x, acc.x);
                acc.y = fmaf(ww[q], vv[q].y, acc.y);
                acc.z = fmaf(ww[q], vv[q].z, acc.z);
                acc.w = fmaf(ww[q], vv[q].w, acc.w);
            }
        }
        for (; t < jn; t++) {
            const int rr = __shfl_sync(0xffffffffu, eid, t);
            const float w = __shfl_sync(0xffffffffu, wv, t);
            const float4 v = ldb4(c2b + (size_t)rr * DD + lane * 4);
            acc.x = fmaf(w, v.x, acc.x); acc.y = fmaf(w, v.y, acc.y);
            acc.z = fmaf(w, v.z, acc.z); acc.w = fmaf(w, v.w, acc.w);
        }
    }
    acc.x *= dn; acc.y *= dn; acc.z *= dn; acc.w *= dn;
    stb4(aggb + (size_t)n * DD + lane * 4, acc);
}

// ---------------- final: logits + log_softmax ----------------
__global__ void __launch_bounds__(128) final_kernel(
    const float* __restrict__ h, const float* __restrict__ Wf,
    const float* __restrict__ fb, float* __restrict__ out)
{
    __shared__ float Wsh[DD * CC];
    __shared__ float bsh[CC];
    __shared__ float rowbuf[4][DD];
    const int tid = threadIdx.x;
    for (int i = tid; i < DD * CC; i += 128) Wsh[i] = Wf[i];
    if (tid < CC) bsh[tid] = fb[tid];
    __syncthreads();

    const int wid = tid >> 5, lane = tid & 31;
    const int rbase = blockIdx.x * 32 + wid * 8;
    const bool has1 = (lane < CC - 32);

    for (int ri = 0; ri < 8; ri++) {
        const int r = rbase + ri;
        if (r >= NN) return;
        float4 v = *(const float4*)(h + (size_t)r * DD + lane * 4);
        *(float4*)(&rowbuf[wid][lane * 4]) = v;
        __syncwarp();
        float acc0 = bsh[lane];
        float acc1 = has1 ? bsh[32 + lane] : 0.f;
#pragma unroll 4
        for (int k = 0; k < DD; k++) {
            float hv = rowbuf[wid][k];
            acc0 = fmaf(hv, Wsh[k * CC + lane], acc0);
            if (has1) acc1 = fmaf(hv, Wsh[k * CC + 32 + lane], acc1);
        }
        float m = has1 ? fmaxf(acc0, acc1) : acc0;
#pragma unroll
        for (int o = 16; o > 0; o >>= 1) m = fmaxf(m, __shfl_xor_sync(0xffffffffu, m, o));
        float s = expf(acc0 - m) + (has1 ? expf(acc1 - m) : 0.f);
#pragma unroll
        for (int o = 16; o > 0; o >>= 1) s += __shfl_xor_sync(0xffffffffu, s, o);
        const float ls = logf(s);
        out[(size_t)r * CC + lane] = acc0 - m - ls;
        if (has1) out[(size_t)r * CC + 32 + lane] = acc1 - m - ls;
        __syncwarp();
    }
}

// ---------------- launch ----------------
extern "C" void kernel_launch(void* const* d_in, const int* in_sizes, int n_in,
                              void* d_out, int out_size)
{
    const float* x       = (const float*)d_in[0];
    const int*   ei      = (const int*)  d_in[1];
    const float* start_W = (const float*)d_in[2];
    const float* start_b = (const float*)d_in[3];
    const float* ln1_g   = (const float*)d_in[4];
    const float* ln1_b   = (const float*)d_in[5];
    const float* convW   = (const float*)d_in[6];
    const float* convB   = (const float*)d_in[7];
    const float* alpha_g = (const float*)d_in[8];
    const float* ln2_g   = (const float*)d_in[9];
    const float* ln2_b   = (const float*)d_in[10];
    const float* ffwW    = (const float*)d_in[11];
    const float* ffwB    = (const float*)d_in[12];
    const float* alpha_f = (const float*)d_in[13];
    const float* final_W = (const float*)d_in[14];
    const float* final_b = (const float*)d_in[15];
    float* out = (float*)d_out;

    float *h, *dinv;
    __nv_bfloat16 *c2b, *aggb, *wb, *w0hi, *w0lo;
    int *counts, *off, *cur, *eidx, *part;
    cudaGetSymbolAddress((void**)&h, g_h);
    cudaGetSymbolAddress((void**)&c2b, g_c2b);
    cudaGetSymbolAddress((void**)&aggb, g_aggb);
    cudaGetSymbolAddress((void**)&wb, g_wb);
    cudaGetSymbolAddress((void**)&w0hi, g_w0hi);
    cudaGetSymbolAddress((void**)&w0lo, g_w0lo);
    cudaGetSymbolAddress((void**)&dinv, g_dinv);
    cudaGetSymbolAddress((void**)&counts, g_counts);
    cudaGetSymbolAddress((void**)&off, g_off);
    cudaGetSymbolAddress((void**)&cur, g_cur);
    cudaGetSymbolAddress((void**)&eidx, g_eidx);
    cudaGetSymbolAddress((void**)&part, g_part);

    const int* rowi = ei;
    const int* coli = ei + NE;

    cudaFuncSetAttribute(gemm_bf16_kernel<0>, cudaFuncAttributeMaxDynamicSharedMemorySize, SM_M0);
    cudaFuncSetAttribute(gemm_bf16_kernel<2>, cudaFuncAttributeMaxDynamicSharedMemorySize, SM_M2);
    cudaFuncSetAttribute(gemm1_kernel, cudaFuncAttributeMaxDynamicSharedMemorySize, SM_G1);

    const int GB = (NN + 63) / 64;
    const int G1 = (NN + 127) / 128;
    const int NW = DD * DD + 2 * NL * DD * DD;

    // gemm1_kernel at capture slot #4
    convert_w_kernel<<<(NW + 255) / 256, 256>>>(start_W, convW, ffwW, w0hi, w0lo, wb);   // 1
    gemm_bf16_kernel<0><<<GB, 256, SM_M0>>>(x, w0hi, w0lo, start_b,                       // 2
                                            nullptr, nullptr, nullptr, nullptr,
                                            nullptr, nullptr, h);
    zero_counts_kernel<<<(NN + 255) / 256, 256>>>(counts);                                // 3
    gemm1_kernel<<<G1, 256, SM_G1>>>(h, wb, ln1_g, ln1_b, c2b);                           // 4 (capture)
    count_kernel<<<(NE + 255) / 256, 256>>>(coli, counts);                                // 5
    dinv_kernel<<<(NN + 255) / 256, 256>>>(counts, dinv);
    scan_block_kernel<<<NB_SCAN, 1024>>>(counts, off, part);
    scan_part_kernel<<<1, 32>>>(part, off);
    add_carry_kernel<<<(NN + 255) / 256, 256>>>(counts, off, part, cur);
    fill_kernel<<<(NE + 255) / 256, 256>>>(rowi, coli, cur, eidx);

    for (int i = 0; i < NL; i++) {
        if (i > 0)
            gemm1_kernel<<<G1, 256, SM_G1>>>(h, wb + (size_t)i * DD * DD,
                                             ln1_g + i * DD, ln1_b + i * DD, c2b);
        gather_kernel<<<(NN + 7) / 8, 256>>>(off, eidx, dinv, c2b, aggb);
        gemm_bf16_kernel<2><<<GB, 256, SM_M2>>>(h, wb + (size_t)(NL + i) * DD * DD, nullptr,
                                                ffwB + i * DD,
                                                ln2_g + i * DD, ln2_b + i * DD,
                                                aggb, convB + i * DD,
                                                alpha_g + i, alpha_f + i, h);
    }

    final_kernel<<<(NN + 31) / 32, 128>>>(h, final_W, final_b, out);
}